// round 10
// baseline (speedup 1.0000x reference)
#include <cuda_runtime.h>
#include <cuda_fp16.h>
#include <math.h>
#include <stdint.h>

// ---------------- problem constants ----------------
#define BATCH   64
#define SEQ     512
#define EDIM    512
#define HDIM    1024
#define VOCAB   32000
#define M0      (BATCH*SEQ)      // 32768 level-0 nodes

// ---------------- device scratch (allocation-free rule) ----------------
__device__ half  g_EMBh[(size_t)VOCAB * EDIM];
__device__ half  g_EMBl[(size_t)VOCAB * EDIM];
__device__ half  g_HB0h[(size_t)M0 * HDIM];
__device__ half  g_HB0l[(size_t)M0 * HDIM];
__device__ half  g_HB1h[(size_t)(M0/2) * HDIM];
__device__ half  g_HB1l[(size_t)(M0/2) * HDIM];
__device__ half  g_RHh [(size_t)(M0/2) * 2 * HDIM];
__device__ half  g_RHl [(size_t)(M0/2) * 2 * HDIM];
__device__ half  g_W0h [(size_t)(2*HDIM) * EDIM];      // [2048][512]  K-major
__device__ half  g_W0l [(size_t)(2*HDIM) * EDIM];
__device__ half  g_UZRh[(size_t)(2*HDIM) * (2*HDIM)];  // [2048][2048]
__device__ half  g_UZRl[(size_t)(2*HDIM) * (2*HDIM)];
__device__ half  g_UHh [(size_t)HDIM * (2*HDIM)];      // [1024][2048]
__device__ half  g_UHl [(size_t)HDIM * (2*HDIM)];
__device__ float g_PRE[(size_t)M0 * 2 * HDIM];         // level-0 pre-activations only
__device__ float g_Z  [(size_t)(M0/2) * HDIM];         // z gate
__device__ float g_BL0[2*HDIM];
__device__ float g_BZR[2*HDIM];
__device__ float g_BH [HDIM];

// ================= helpers =================
__device__ __forceinline__ uint32_t smem_u32(const void* p) {
    uint32_t a;
    asm("{ .reg .u64 t; cvta.to.shared.u64 t, %1; cvt.u32.u64 %0, t; }" : "=r"(a) : "l"(p));
    return a;
}
__device__ __forceinline__ void split1(float v, half& h, half& l) {
    h = __float2half_rn(v);
    l = __float2half_rn(v - __half2float(h));
}
__device__ __forceinline__ void split2u(float a, float b, uint32_t& uh, uint32_t& ul) {
    half ha, la, hb, lb;
    split1(a, ha, la); split1(b, hb, lb);
    __half2 H = __halves2half2(ha, hb), L = __halves2half2(la, lb);
    uh = *(uint32_t*)&H; ul = *(uint32_t*)&L;
}
// read 2 consecutive elements as hi+lo fp32
__device__ __forceinline__ float2 ld2hl(const half* ph, const half* pl) {
    uint32_t uh = *(const uint32_t*)ph, ul = *(const uint32_t*)pl;
    float2 fh = __half22float2(*(__half2*)&uh), fl = __half22float2(*(__half2*)&ul);
    return make_float2(fh.x + fl.x, fh.y + fl.y);
}
__device__ __forceinline__ void st4split(half* ph, half* pl, float4 v) {
    uint32_t h0, l0, h1, l1;
    split2u(v.x, v.y, h0, l0);
    split2u(v.z, v.w, h1, l1);
    uint2 uh, ul;
    uh.x = h0; uh.y = h1; ul.x = l0; ul.y = l1;
    *(uint2*)ph = uh; *(uint2*)pl = ul;
}

#define CP16(dst, src) asm volatile("cp.async.cg.shared.global [%0], [%1], 16;" :: "r"(dst), "l"(src))
#define CP_COMMIT()    asm volatile("cp.async.commit_group;" ::: "memory")
#define CP_WAIT(n)     asm volatile("cp.async.wait_group %0;" :: "n"(n) : "memory")

#define LDSM4(r0, r1, r2, r3, addr)                                              \
    asm volatile("ldmatrix.sync.aligned.m8n8.x4.shared.b16 {%0,%1,%2,%3}, [%4];" \
        : "=r"(r0), "=r"(r1), "=r"(r2), "=r"(r3) : "r"(addr))

#define MMA16816(d, a, b0, b1)                                                   \
    asm volatile("mma.sync.aligned.m16n8k16.row.col.f32.f16.f16.f32 "            \
        "{%0,%1,%2,%3}, {%4,%5,%6,%7}, {%8,%9}, {%0,%1,%2,%3};"                  \
        : "+f"((d)[0]), "+f"((d)[1]), "+f"((d)[2]), "+f"((d)[3])                  \
        : "r"((a)[0]), "r"((a)[1]), "r"((a)[2]), "r"((a)[3]), "r"(b0), "r"(b1))

__device__ __forceinline__ float sigmf(float x) { return 1.f / (1.f + expf(-x)); }

// ================= packing kernels =================
__global__ void transpose_split_kernel(const float* __restrict__ src,
                                       half* __restrict__ dh, half* __restrict__ dl,
                                       int R, int C, int dpitch)
{
    __shared__ float t[32][33];
    int c0 = blockIdx.x * 32, r0 = blockIdx.y * 32;
    int x = threadIdx.x, y = threadIdx.y;   // 32 x 8
    #pragma unroll
    for (int i = 0; i < 32; i += 8) {
        int r = r0 + y + i, c = c0 + x;
        t[y + i][x] = (r < R && c < C) ? src[(size_t)r * C + c] : 0.f;
    }
    __syncthreads();
    #pragma unroll
    for (int i = 0; i < 32; i += 8) {
        int c = c0 + y + i, r = r0 + x;
        if (c < C && r < R) {
            float v = t[x][y + i];
            half h, l; split1(v, h, l);
            dh[(size_t)c * dpitch + r] = h;
            dl[(size_t)c * dpitch + r] = l;
        }
    }
}

__global__ void emb_split_kernel(const float* __restrict__ emb,
                                 half* __restrict__ eh, half* __restrict__ el, int total4)
{
    int q = blockIdx.x * blockDim.x + threadIdx.x;
    if (q >= total4) return;
    int idx = q * 4;
    float4 v = *(const float4*)(emb + idx);
    st4split(eh + idx, el + idx, v);
}

__global__ void bias_kernel(
    const float* __restrict__ bz,  const float* __restrict__ bzl, const float* __restrict__ bzr,
    const float* __restrict__ br,  const float* __restrict__ brl, const float* __restrict__ brr,
    const float* __restrict__ bh,  const float* __restrict__ bhl, const float* __restrict__ bhr)
{
    int i = blockIdx.x * blockDim.x + threadIdx.x;
    if (i >= 1024) return;
    float bzs = bz[i] + bzl[i] + bzr[i];
    float brs = br[i] + brl[i] + brr[i];
    float bhs = bh[i] + bhl[i] + bhr[i];
    g_BZR[i] = bzs; g_BZR[1024 + i] = brs;
    g_BH[i]  = bhs;
    g_BL0[i] = bzs; g_BL0[1024 + i] = bhs;
}

// level 0: pre = [zpre | hpre] (M x 2048) -> h0 = (1-z)*tanh(hpre) -> hi/lo planes
__global__ void e0_kernel(const float* __restrict__ pre,
                          half* __restrict__ hh, half* __restrict__ hl, int total4)
{
    int q = blockIdx.x * blockDim.x + threadIdx.x;
    if (q >= total4) return;
    int idx = q * 4;
    int m = idx >> 10, j = idx & 1023;
    size_t o = (size_t)m * 2048 + j;
    float4 zp = *(const float4*)(pre + o);
    float4 hp = *(const float4*)(pre + o + 1024);
    float4 r;
    r.x = (1.f - sigmf(zp.x)) * tanhf(hp.x);
    r.y = (1.f - sigmf(zp.y)) * tanhf(hp.y);
    r.z = (1.f - sigmf(zp.z)) * tanhf(hp.z);
    r.w = (1.f - sigmf(zp.w)) * tanhf(hp.w);
    st4split(hh + idx, hl + idx, r);
}

// ================= fp16x3 mma GEMM, cp.async 3-stage, fused epilogues =================
// MODE 0: C = acc + bias (fp32 store, level-0)
// MODE 1: GEMM1+e1: z-tiles (bn<1024) -> zb; r-tiles -> rh hi/lo planes (reads hprev)
// MODE 2: GEMM2+e2: h = z*(hl+hr) + (1-z)*tanh(acc+bias) -> planes or fp32 out
#define BM 64
#define BN 128
#define BK 32
#define PAD_B 80
#define OA_H 0
#define OA_L (64 * PAD_B)
#define OB_H (2 * 64 * PAD_B)
#define OB_L (OB_H + 128 * PAD_B)
#define STAGE_BYTES (OB_L + 128 * PAD_B)  // 30720
#define NSTAGE 3
#define SMEM_BYTES (NSTAGE * STAGE_BYTES) // 92160

template<int MODE, bool GATHER>
__global__ void __launch_bounds__(128, 2)
gemm_mma_kernel(const half* __restrict__ Ah, const half* __restrict__ Al,
                const int* __restrict__ tok,
                const half* __restrict__ Bh, const half* __restrict__ Bl,
                const float* __restrict__ bias,
                float* __restrict__ C,                 // MODE 0 output
                float* __restrict__ zb,                // MODE 1 out / MODE 2 in
                const half* __restrict__ hph, const half* __restrict__ hpl,  // prev level planes
                half* __restrict__ outh, half* __restrict__ outl,            // MODE1: rh, MODE2: h
                float* __restrict__ outf,              // MODE 2 final fp32 (or null)
                int M, int N, int K)
{
    extern __shared__ char smem[];
    const uint32_t sb = smem_u32(smem);
    const int tid  = threadIdx.x;
    const int lane = tid & 31;
    const int wid  = tid >> 5;
    const int warp_m = wid & 1;
    const int warp_n = wid >> 1;
    const int bm = blockIdx.y * BM, bn = blockIdx.x * BN;

    // ---- cp.async mapping: 12 x 16B per thread per stage ----
    const int r0  = tid >> 2;
    const int seg = (tid & 3) * 16;
    const char* srcp[12];
    uint32_t    dsto[12];
    #pragma unroll
    for (int i = 0; i < 12; i++) {
        if (i < 4) {
            int rl = r0 + 32 * (i & 1);
            int gr = bm + rl;
            size_t ar = GATHER ? (size_t)__ldg(&tok[gr]) : (size_t)gr;
            const half* base = (i < 2) ? Ah : Al;
            srcp[i] = (const char*)(base + ar * K) + seg;
            dsto[i] = ((i < 2) ? OA_H : OA_L) + (uint32_t)(rl * PAD_B + seg);
        } else {
            int j  = (i - 4) & 3;
            int rl = r0 + 32 * j;
            const half* base = (i < 8) ? Bh : Bl;
            srcp[i] = (const char*)(base + (size_t)(bn + rl) * K) + seg;
            dsto[i] = ((i < 8) ? OB_H : OB_L) + (uint32_t)(rl * PAD_B + seg);
        }
    }

    const int NT = K / BK;
    auto issue = [&](int kt) {
        if (kt < NT) {
            const uint32_t d = sb + (kt % NSTAGE) * STAGE_BYTES;
            const size_t g = (size_t)kt * 64;
            #pragma unroll
            for (int i = 0; i < 12; i++) CP16(d + dsto[i], srcp[i] + g);
        }
        CP_COMMIT();
    };

    const uint32_t a_lane_off = (uint32_t)((warp_m * 32 + (lane & 15)) * PAD_B + ((lane >> 4) * 8) * 2);
    const uint32_t b_lane_off = (uint32_t)((warp_n * 64 + ((lane >> 4) << 3) + (lane & 7)) * PAD_B
                                           + (((lane >> 3) & 1) * 8) * 2);

    float acc[2][8][4];
    #pragma unroll
    for (int mt = 0; mt < 2; mt++)
        #pragma unroll
        for (int t = 0; t < 8; t++)
            #pragma unroll
            for (int j = 0; j < 4; j++) acc[mt][t][j] = 0.f;

    issue(0);
    issue(1);

    for (int kt = 0; kt < NT; kt++) {
        CP_WAIT(1);
        __syncthreads();
        issue(kt + 2);

        const uint32_t sbase = sb + (kt % NSTAGE) * STAGE_BYTES;
        #pragma unroll
        for (int ks = 0; ks < 2; ks++) {
            const uint32_t koff = ks * 32;
            uint32_t ah[2][4], al[2][4], bh[4][4], bl[4][4];
            #pragma unroll
            for (int mt = 0; mt < 2; mt++) {
                uint32_t ad = sbase + a_lane_off + mt * (16 * PAD_B) + koff;
                LDSM4(ah[mt][0], ah[mt][1], ah[mt][2], ah[mt][3], ad + OA_H);
                LDSM4(al[mt][0], al[mt][1], al[mt][2], al[mt][3], ad + OA_L);
            }
            #pragma unroll
            for (int ng = 0; ng < 4; ng++) {
                uint32_t bd = sbase + b_lane_off + ng * (16 * PAD_B) + koff;
                LDSM4(bh[ng][0], bh[ng][1], bh[ng][2], bh[ng][3], bd + OB_H);
                LDSM4(bl[ng][0], bl[ng][1], bl[ng][2], bl[ng][3], bd + OB_L);
            }
            #pragma unroll
            for (int mt = 0; mt < 2; mt++)
                #pragma unroll
                for (int ng = 0; ng < 4; ng++)
                    #pragma unroll
                    for (int p = 0; p < 2; p++) {
                        float* c = acc[mt][ng * 2 + p];
                        MMA16816(c, ah[mt], bh[ng][2 * p], bh[ng][2 * p + 1]);
                        MMA16816(c, ah[mt], bl[ng][2 * p], bl[ng][2 * p + 1]);
                        MMA16816(c, al[mt], bh[ng][2 * p], bh[ng][2 * p + 1]);
                    }
        }
    }

    // ---- fused epilogue ----
    const int r0e = bm + warp_m * 32 + (lane >> 2);
    const int c0e = bn + warp_n * 64 + (lane & 3) * 2;
    const bool ztile = (MODE == 1) && (bn < 1024);

    #pragma unroll
    for (int mt = 0; mt < 2; mt++) {
        #pragma unroll
        for (int t = 0; t < 8; t++) {
            const int col = c0e + t * 8;
            const float b0 = bias[col], b1 = bias[col + 1];
            #pragma unroll
            for (int p = 0; p < 2; p++) {
                const int rr = r0e + mt * 16 + p * 8;
                const float v0 = acc[mt][t][2 * p] + b0;
                const float v1 = acc[mt][t][2 * p + 1] + b1;

                if (MODE == 0) {
                    *(float2*)(C + (size_t)rr * N + col) = make_float2(v0, v1);
                } else if (MODE == 1) {
                    if (ztile) {
                        *(float2*)(zb + (size_t)rr * 1024 + col) =
                            make_float2(sigmf(v0), sigmf(v1));
                    } else {
                        const int j = col - 1024;
                        const size_t o = (size_t)rr * 2048 + j;
                        const float rg0 = sigmf(v0), rg1 = sigmf(v1);
                        float2 hl2 = ld2hl(hph + o,        hpl + o);
                        float2 hr2 = ld2hl(hph + o + 1024, hpl + o + 1024);
                        uint32_t uh, ul;
                        split2u(rg0 * hl2.x, rg1 * hl2.y, uh, ul);
                        *(uint32_t*)(outh + o) = uh; *(uint32_t*)(outl + o) = ul;
                        split2u(rg0 * hr2.x, rg1 * hr2.y, uh, ul);
                        *(uint32_t*)(outh + o + 1024) = uh; *(uint32_t*)(outl + o + 1024) = ul;
                    }
                } else { // MODE == 2
                    const size_t o = (size_t)rr * 2048 + col;
                    float2 z2  = *(const float2*)(zb + (size_t)rr * 1024 + col);
                    float2 hl2 = ld2hl(hph + o,        hpl + o);
                    float2 hr2 = ld2hl(hph + o + 1024, hpl + o + 1024);
                    float h0 = z2.x * (hl2.x + hr2.x) + (1.f - z2.x) * tanhf(v0);
                    float h1 = z2.y * (hl2.y + hr2.y) + (1.f - z2.y) * tanhf(v1);
                    if (outf) {
                        *(float2*)(outf + (size_t)rr * 1024 + col) = make_float2(h0, h1);
                    } else {
                        uint32_t uh, ul;
                        split2u(h0, h1, uh, ul);
                        *(uint32_t*)(outh + (size_t)rr * 1024 + col) = uh;
                        *(uint32_t*)(outl + (size_t)rr * 1024 + col) = ul;
                    }
                }
            }
        }
    }
}

// ================= launch =================
extern "C" void kernel_launch(void* const* d_in, const int* in_sizes, int n_in,
                              void* d_out, int out_size)
{
    const int*   tokens = (const int*)  d_in[0];
    const float* emb    = (const float*)d_in[1];
    const float* W_z  = (const float*)d_in[2];
    const float* b_z  = (const float*)d_in[3];
    const float* U_zl = (const float*)d_in[4];
    const float* b_zl = (const float*)d_in[5];
    const float* U_zr = (const float*)d_in[6];
    const float* b_zr = (const float*)d_in[7];
    const float* W_r  = (const float*)d_in[8];
    const float* b_r  = (const float*)d_in[9];
    const float* U_rl = (const float*)d_in[10];
    const float* b_rl = (const float*)d_in[11];
    const float* U_rr = (const float*)d_in[12];
    const float* b_rr = (const float*)d_in[13];
    const float* W_h  = (const float*)d_in[14];
    const float* b_h  = (const float*)d_in[15];
    const float* U_hl = (const float*)d_in[16];
    const float* b_hl = (const float*)d_in[17];
    const float* U_hr = (const float*)d_in[18];
    const float* b_hr = (const float*)d_in[19];
    (void)W_r; // level-0 r is multiplied by hl=hr=0

    half *EMBh, *EMBl, *HB0h, *HB0l, *HB1h, *HB1l, *RHh, *RHl;
    half *W0h, *W0l, *UZRh, *UZRl, *UHh, *UHl;
    float *PRE, *ZB, *BL0, *BZR, *BH;
    cudaGetSymbolAddress((void**)&EMBh, g_EMBh);
    cudaGetSymbolAddress((void**)&EMBl, g_EMBl);
    cudaGetSymbolAddress((void**)&HB0h, g_HB0h);
    cudaGetSymbolAddress((void**)&HB0l, g_HB0l);
    cudaGetSymbolAddress((void**)&HB1h, g_HB1h);
    cudaGetSymbolAddress((void**)&HB1l, g_HB1l);
    cudaGetSymbolAddress((void**)&RHh,  g_RHh);
    cudaGetSymbolAddress((void**)&RHl,  g_RHl);
    cudaGetSymbolAddress((void**)&W0h,  g_W0h);
    cudaGetSymbolAddress((void**)&W0l,  g_W0l);
    cudaGetSymbolAddress((void**)&UZRh, g_UZRh);
    cudaGetSymbolAddress((void**)&UZRl, g_UZRl);
    cudaGetSymbolAddress((void**)&UHh,  g_UHh);
    cudaGetSymbolAddress((void**)&UHl,  g_UHl);
    cudaGetSymbolAddress((void**)&PRE,  g_PRE);
    cudaGetSymbolAddress((void**)&ZB,   g_Z);
    cudaGetSymbolAddress((void**)&BL0,  g_BL0);
    cudaGetSymbolAddress((void**)&BZR,  g_BZR);
    cudaGetSymbolAddress((void**)&BH,   g_BH);

    cudaFuncSetAttribute(gemm_mma_kernel<0, true>,
                         cudaFuncAttributeMaxDynamicSharedMemorySize, SMEM_BYTES);
    cudaFuncSetAttribute(gemm_mma_kernel<1, false>,
                         cudaFuncAttributeMaxDynamicSharedMemorySize, SMEM_BYTES);
    cudaFuncSetAttribute(gemm_mma_kernel<2, false>,
                         cudaFuncAttributeMaxDynamicSharedMemorySize, SMEM_BYTES);

    dim3 blk(32, 8);
    dim3 g32(1024 / 32, 1024 / 32);
    dim3 gW(1024 / 32, 512 / 32);

    // ---- launches 0..4: minimal prerequisites for the level-0 GEMM ----
    transpose_split_kernel<<<gW, blk>>>(W_z, W0h, W0l, 512, 1024, 512);                              // 0
    transpose_split_kernel<<<gW, blk>>>(W_h, W0h + (size_t)1024*512, W0l + (size_t)1024*512,
                                        512, 1024, 512);                                              // 1
    bias_kernel<<<4, 256>>>(b_z, b_zl, b_zr, b_r, b_rl, b_rr, b_h, b_hl, b_hr);                       // 2
    {
        int etotal4 = VOCAB * EDIM / 4;
        emb_split_kernel<<<(etotal4 + 255) / 256, 256>>>(emb, EMBh, EMBl, etotal4);                   // 3
    }
    transpose_split_kernel<<<g32, blk>>>(U_zl, UZRh, UZRl, 1024, 1024, 2048);                         // 4

    // ---- launch 5: level-0 GEMM (ncu -s 5 captures this) ----
    {
        dim3 grid(2 * HDIM / BN, M0 / BM);
        gemm_mma_kernel<0, true><<<grid, 128, SMEM_BYTES>>>(
            EMBh, EMBl, tokens, W0h, W0l, BL0, PRE,
            nullptr, nullptr, nullptr, nullptr, nullptr, nullptr, M0, 2 * HDIM, EDIM);
    }
    {
        int total4 = M0 * HDIM / 4;
        e0_kernel<<<(total4 + 255) / 256, 256>>>(PRE, HB0h, HB0l, total4);                            // 6
    }

    // ---- remaining weight packing (before first level-GEMM use) ----
    transpose_split_kernel<<<g32, blk>>>(U_rl, UZRh + (size_t)1024*2048, UZRl + (size_t)1024*2048,
                                         1024, 1024, 2048);                                           // 7
    transpose_split_kernel<<<g32, blk>>>(U_zr, UZRh + 1024, UZRl + 1024, 1024, 1024, 2048);           // 8
    transpose_split_kernel<<<g32, blk>>>(U_rr, UZRh + (size_t)1024*2048 + 1024,
                                         UZRl + (size_t)1024*2048 + 1024, 1024, 1024, 2048);          // 9
    transpose_split_kernel<<<g32, blk>>>(U_hl, UHh, UHl, 1024, 1024, 2048);                           // 10
    transpose_split_kernel<<<g32, blk>>>(U_hr, UHh + 1024, UHl + 1024, 1024, 1024, 2048);             // 11

    // ---- tree levels: n = 512 -> 1 (2 fused kernels per level) ----
    half* hph = HB0h; half* hpl = HB0l;
    int n = SEQ, lvl = 0;
    while (n > 1) {
        int Mn = BATCH * (n / 2);
        bool final = (n / 2 == 1);
        half* hoh = (lvl & 1) ? HB0h : HB1h;
        half* hol = (lvl & 1) ? HB0l : HB1l;
        int gy = Mn / BM;

        // GEMM1 + e1: z-tiles -> ZB; r-tiles -> RH planes
        {
            dim3 grid(2 * HDIM / BN, gy);
            gemm_mma_kernel<1, false><<<grid, 128, SMEM_BYTES>>>(
                hph, hpl, nullptr, UZRh, UZRl, BZR,
                nullptr, ZB, hph, hpl, RHh, RHl, nullptr, Mn, 2 * HDIM, 2 * HDIM);
        }
        // GEMM2 + e2: h = z*(hl+hr) + (1-z)*tanh(.) -> planes or final fp32
        {
            dim3 grid(HDIM / BN, gy);
            gemm_mma_kernel<2, false><<<grid, 128, SMEM_BYTES>>>(
                RHh, RHl, nullptr, UHh, UHl, BH,
                nullptr, ZB, hph, hpl, hoh, hol,
                final ? (float*)d_out : nullptr, Mn, HDIM, 2 * HDIM);
        }

        hph = hoh; hpl = hol;
        n /= 2;
        lvl++;
    }
    (void)in_sizes; (void)n_in; (void)out_size;
}

// round 11
// speedup vs baseline: 1.0568x; 1.0568x over previous
#include <cuda_runtime.h>
#include <cuda_fp16.h>
#include <math.h>
#include <stdint.h>

// ---------------- problem constants ----------------
#define BATCH   64
#define SEQ     512
#define EDIM    512
#define HDIM    1024
#define VOCAB   32000
#define M0      (BATCH*SEQ)      // 32768 level-0 nodes

// ---------------- device scratch (allocation-free rule) ----------------
__device__ half  g_EMBh[(size_t)VOCAB * EDIM];
__device__ half  g_EMBl[(size_t)VOCAB * EDIM];
__device__ half  g_HB0h[(size_t)M0 * HDIM];
__device__ half  g_HB0l[(size_t)M0 * HDIM];
__device__ half  g_HB1h[(size_t)(M0/2) * HDIM];
__device__ half  g_HB1l[(size_t)(M0/2) * HDIM];
__device__ half  g_RHh [(size_t)(M0/2) * 2 * HDIM];
__device__ half  g_RHl [(size_t)(M0/2) * 2 * HDIM];
__device__ half  g_W0h [(size_t)(2*HDIM) * EDIM];      // [2048][512]  K-major
__device__ half  g_W0l [(size_t)(2*HDIM) * EDIM];
__device__ half  g_UZRh[(size_t)(2*HDIM) * (2*HDIM)];  // [2048][2048]
__device__ half  g_UZRl[(size_t)(2*HDIM) * (2*HDIM)];
__device__ half  g_UHh [(size_t)HDIM * (2*HDIM)];      // [1024][2048]
__device__ half  g_UHl [(size_t)HDIM * (2*HDIM)];
__device__ float g_PRE[(size_t)M0 * 2 * HDIM];
__device__ float g_Z  [(size_t)(M0/2) * HDIM];
__device__ float g_BL0[2*HDIM];
__device__ float g_BZR[2*HDIM];
__device__ float g_BH [HDIM];

// ================= helpers =================
__device__ __forceinline__ uint32_t smem_u32(const void* p) {
    uint32_t a;
    asm("{ .reg .u64 t; cvta.to.shared.u64 t, %1; cvt.u32.u64 %0, t; }" : "=r"(a) : "l"(p));
    return a;
}
__device__ __forceinline__ void split1(float v, half& h, half& l) {
    h = __float2half_rn(v);
    l = __float2half_rn(v - __half2float(h));
}
__device__ __forceinline__ float4 ld4h(const half* p) {
    uint2 u = *(const uint2*)p;
    __half2 a = *(__half2*)&u.x, b = *(__half2*)&u.y;
    float2 fa = __half22float2(a), fb = __half22float2(b);
    return make_float4(fa.x, fa.y, fb.x, fb.y);
}
__device__ __forceinline__ void st4split(half* ph, half* pl, float4 v) {
    half h0, l0, h1, l1, h2, l2, h3, l3;
    split1(v.x, h0, l0); split1(v.y, h1, l1);
    split1(v.z, h2, l2); split1(v.w, h3, l3);
    __half2 H0 = __halves2half2(h0, h1), H1 = __halves2half2(h2, h3);
    __half2 L0 = __halves2half2(l0, l1), L1 = __halves2half2(l2, l3);
    uint2 uh, ul;
    uh.x = *(uint32_t*)&H0; uh.y = *(uint32_t*)&H1;
    ul.x = *(uint32_t*)&L0; ul.y = *(uint32_t*)&L1;
    *(uint2*)ph = uh; *(uint2*)pl = ul;
}

#define CP16(dst, src) asm volatile("cp.async.cg.shared.global [%0], [%1], 16;" :: "r"(dst), "l"(src))
#define CP_COMMIT()    asm volatile("cp.async.commit_group;" ::: "memory")
#define CP_WAIT(n)     asm volatile("cp.async.wait_group %0;" :: "n"(n) : "memory")

#define LDSM4(r0, r1, r2, r3, addr)                                              \
    asm volatile("ldmatrix.sync.aligned.m8n8.x4.shared.b16 {%0,%1,%2,%3}, [%4];" \
        : "=r"(r0), "=r"(r1), "=r"(r2), "=r"(r3) : "r"(addr))

#define MMA16816(d, a, b0, b1)                                                   \
    asm volatile("mma.sync.aligned.m16n8k16.row.col.f32.f16.f16.f32 "            \
        "{%0,%1,%2,%3}, {%4,%5,%6,%7}, {%8,%9}, {%0,%1,%2,%3};"                  \
        : "+f"((d)[0]), "+f"((d)[1]), "+f"((d)[2]), "+f"((d)[3])                  \
        : "r"((a)[0]), "r"((a)[1]), "r"((a)[2]), "r"((a)[3]), "r"(b0), "r"(b1))

__device__ __forceinline__ float sigmf(float x) { return 1.f / (1.f + expf(-x)); }

// ================= megapack: ONE kernel does all weight/emb packing =================
// block layout (256 threads each):
//   [0, NB_EMB)            emb split
//   [NB_EMB, +512)         W_z transpose  (512x1024 -> W0 planes, dpitch 512)
//   [.., +512)             W_h transpose
//   [.., +4)               bias fold
//   [.., +1024) x6         U_zl, U_rl, U_zr, U_rr -> UZR planes; U_hl, U_hr -> UH planes
#define NB_EMB   16000
#define NB_W     512
#define NB_U     1024

struct PackArgs {
    const float *emb, *Wz, *Wh, *Uzl, *Url, *Uzr, *Urr, *Uhl, *Uhr;
    const float *bz, *bzl, *bzr, *br, *brl, *brr, *bh, *bhl, *bhr;
};

__device__ void do_transpose_split(const float* __restrict__ src,
                                   half* __restrict__ dh, half* __restrict__ dl,
                                   int R, int C, int dpitch, int blk, int tid)
{
    __shared__ float t[32][33];
    int gx = C / 32;
    int c0 = (blk % gx) * 32, r0 = (blk / gx) * 32;
    int x = tid & 31, y = tid >> 5;   // 32 x 8
    #pragma unroll
    for (int i = 0; i < 32; i += 8) {
        t[y + i][x] = src[(size_t)(r0 + y + i) * C + (c0 + x)];
    }
    __syncthreads();
    #pragma unroll
    for (int i = 0; i < 32; i += 8) {
        int c = c0 + y + i, r = r0 + x;
        float v = t[x][y + i];
        half h, l; split1(v, h, l);
        dh[(size_t)c * dpitch + r] = h;
        dl[(size_t)c * dpitch + r] = l;
    }
}

__global__ void __launch_bounds__(256) megapack_kernel(PackArgs a)
{
    const int tid = threadIdx.x;
    int blk = blockIdx.x;

    if (blk < NB_EMB) {   // emb split: 4.096M float4 units
        int q = blk * 256 + tid;
        const int total4 = VOCAB * EDIM / 4;
        if (q < total4) {
            int idx = q * 4;
            float4 v = *(const float4*)(a.emb + idx);
            st4split(g_EMBh + idx, g_EMBl + idx, v);
        }
        return;
    }
    blk -= NB_EMB;
    if (blk < 2 * NB_W) { // W0 transposes (512x1024 each, dpitch 512)
        if (blk < NB_W) do_transpose_split(a.Wz, g_W0h, g_W0l, 512, 1024, 512, blk, tid);
        else            do_transpose_split(a.Wh, g_W0h + (size_t)1024*512, g_W0l + (size_t)1024*512,
                                           512, 1024, 512, blk - NB_W, tid);
        return;
    }
    blk -= 2 * NB_W;
    if (blk < 4) {        // bias fold (1024 lanes)
        int i = blk * 256 + tid;
        float bzs = a.bz[i] + a.bzl[i] + a.bzr[i];
        float brs = a.br[i] + a.brl[i] + a.brr[i];
        float bhs = a.bh[i] + a.bhl[i] + a.bhr[i];
        g_BZR[i] = bzs; g_BZR[1024 + i] = brs;
        g_BH[i]  = bhs;
        g_BL0[i] = bzs; g_BL0[1024 + i] = bhs;
        return;
    }
    blk -= 4;
    {   // U transposes: 6 matrices of 1024x1024
        int which = blk / NB_U, b = blk % NB_U;
        switch (which) {
            case 0: do_transpose_split(a.Uzl, g_UZRh, g_UZRl, 1024, 1024, 2048, b, tid); break;
            case 1: do_transpose_split(a.Url, g_UZRh + (size_t)1024*2048, g_UZRl + (size_t)1024*2048,
                                       1024, 1024, 2048, b, tid); break;
            case 2: do_transpose_split(a.Uzr, g_UZRh + 1024, g_UZRl + 1024, 1024, 1024, 2048, b, tid); break;
            case 3: do_transpose_split(a.Urr, g_UZRh + (size_t)1024*2048 + 1024,
                                       g_UZRl + (size_t)1024*2048 + 1024, 1024, 1024, 2048, b, tid); break;
            case 4: do_transpose_split(a.Uhl, g_UHh, g_UHl, 1024, 1024, 2048, b, tid); break;
            default: do_transpose_split(a.Uhr, g_UHh + 1024, g_UHl + 1024, 1024, 1024, 2048, b, tid); break;
        }
    }
}

// ================= fp16x3 mma GEMM, cp.async 3-stage, 128 threads =================
// C(MxN) = (Ah+Al)(MxK) @ (Bh+Bl)(NxK)^T + bias; drop Al*Bl.
// BM=64, BN=128, BK=32. 4 warps: 2m x 2n, warp tile 32x64.
#define BM 64
#define BN 128
#define BK 32
#define PAD_B 80
#define OA_H 0
#define OA_L (64 * PAD_B)
#define OB_H (2 * 64 * PAD_B)
#define OB_L (OB_H + 128 * PAD_B)
#define STAGE_BYTES (OB_L + 128 * PAD_B)  // 30720
#define NSTAGE 3
#define SMEM_BYTES (NSTAGE * STAGE_BYTES) // 92160

template<bool GATHER>
__global__ void __launch_bounds__(128, 2)
gemm_mma_kernel(const half* __restrict__ Ah, const half* __restrict__ Al,
                const int* __restrict__ tok,
                const half* __restrict__ Bh, const half* __restrict__ Bl,
                const float* __restrict__ bias,
                float* __restrict__ C, int M, int N, int K)
{
    extern __shared__ char smem[];
    const uint32_t sb = smem_u32(smem);
    const int tid  = threadIdx.x;
    const int lane = tid & 31;
    const int wid  = tid >> 5;
    const int warp_m = wid & 1;
    const int warp_n = wid >> 1;
    const int bm = blockIdx.y * BM, bn = blockIdx.x * BN;

    const int r0  = tid >> 2;
    const int seg = (tid & 3) * 16;
    const char* srcp[12];
    uint32_t    dsto[12];
    #pragma unroll
    for (int i = 0; i < 12; i++) {
        if (i < 4) {
            int rl = r0 + 32 * (i & 1);
            int gr = bm + rl;
            size_t ar = GATHER ? (size_t)__ldg(&tok[gr]) : (size_t)gr;
            const half* base = (i < 2) ? Ah : Al;
            srcp[i] = (const char*)(base + ar * K) + seg;
            dsto[i] = ((i < 2) ? OA_H : OA_L) + (uint32_t)(rl * PAD_B + seg);
        } else {
            int j  = (i - 4) & 3;
            int rl = r0 + 32 * j;
            const half* base = (i < 8) ? Bh : Bl;
            srcp[i] = (const char*)(base + (size_t)(bn + rl) * K) + seg;
            dsto[i] = ((i < 8) ? OB_H : OB_L) + (uint32_t)(rl * PAD_B + seg);
        }
    }

    const int NT = K / BK;
    auto issue = [&](int kt) {
        if (kt < NT) {
            const uint32_t d = sb + (kt % NSTAGE) * STAGE_BYTES;
            const size_t g = (size_t)kt * 64;
            #pragma unroll
            for (int i = 0; i < 12; i++) CP16(d + dsto[i], srcp[i] + g);
        }
        CP_COMMIT();
    };

    const uint32_t a_lane_off = (uint32_t)((warp_m * 32 + (lane & 15)) * PAD_B + ((lane >> 4) * 8) * 2);
    const uint32_t b_lane_off = (uint32_t)((warp_n * 64 + ((lane >> 4) << 3) + (lane & 7)) * PAD_B
                                           + (((lane >> 3) & 1) * 8) * 2);

    float acc[2][8][4];
    #pragma unroll
    for (int mt = 0; mt < 2; mt++)
        #pragma unroll
        for (int t = 0; t < 8; t++)
            #pragma unroll
            for (int j = 0; j < 4; j++) acc[mt][t][j] = 0.f;

    issue(0);
    issue(1);

    for (int kt = 0; kt < NT; kt++) {
        CP_WAIT(1);
        __syncthreads();
        issue(kt + 2);

        const uint32_t sbase = sb + (kt % NSTAGE) * STAGE_BYTES;
        #pragma unroll
        for (int ks = 0; ks < 2; ks++) {
            const uint32_t koff = ks * 32;
            uint32_t ah[2][4], al[2][4], bh[4][4], bl[4][4];
            #pragma unroll
            for (int mt = 0; mt < 2; mt++) {
                uint32_t ad = sbase + a_lane_off + mt * (16 * PAD_B) + koff;
                LDSM4(ah[mt][0], ah[mt][1], ah[mt][2], ah[mt][3], ad + OA_H);
                LDSM4(al[mt][0], al[mt][1], al[mt][2], al[mt][3], ad + OA_L);
            }
            #pragma unroll
            for (int ng = 0; ng < 4; ng++) {
                uint32_t bd = sbase + b_lane_off + ng * (16 * PAD_B) + koff;
                LDSM4(bh[ng][0], bh[ng][1], bh[ng][2], bh[ng][3], bd + OB_H);
                LDSM4(bl[ng][0], bl[ng][1], bl[ng][2], bl[ng][3], bd + OB_L);
            }
            #pragma unroll
            for (int mt = 0; mt < 2; mt++)
                #pragma unroll
                for (int ng = 0; ng < 4; ng++)
                    #pragma unroll
                    for (int p = 0; p < 2; p++) {
                        float* c = acc[mt][ng * 2 + p];
                        MMA16816(c, ah[mt], bh[ng][2 * p], bh[ng][2 * p + 1]);
                        MMA16816(c, ah[mt], bl[ng][2 * p], bl[ng][2 * p + 1]);
                        MMA16816(c, al[mt], bh[ng][2 * p], bh[ng][2 * p + 1]);
                    }
        }
    }

    const int r0e = bm + warp_m * 32 + (lane >> 2);
    const int c0e = bn + warp_n * 64 + (lane & 3) * 2;
    #pragma unroll
    for (int mt = 0; mt < 2; mt++) {
        const int row = r0e + mt * 16;
        #pragma unroll
        for (int t = 0; t < 8; t++) {
            const int col = c0e + t * 8;
            const float b0 = bias[col], b1 = bias[col + 1];
            float2 v0 = make_float2(acc[mt][t][0] + b0, acc[mt][t][1] + b1);
            *(float2*)(C + (size_t)row * N + col) = v0;
            float2 v1 = make_float2(acc[mt][t][2] + b0, acc[mt][t][3] + b1);
            *(float2*)(C + (size_t)(row + 8) * N + col) = v1;
        }
    }
}

// ================= elementwise epilogues =================
__global__ void e0_kernel(const float* __restrict__ pre,
                          half* __restrict__ hh, half* __restrict__ hl, int total4)
{
    int q = blockIdx.x * blockDim.x + threadIdx.x;
    if (q >= total4) return;
    int idx = q * 4;
    int m = idx >> 10, j = idx & 1023;
    size_t o = (size_t)m * 2048 + j;
    float4 zp = *(const float4*)(pre + o);
    float4 hp = *(const float4*)(pre + o + 1024);
    float4 r;
    r.x = (1.f - sigmf(zp.x)) * tanhf(hp.x);
    r.y = (1.f - sigmf(zp.y)) * tanhf(hp.y);
    r.z = (1.f - sigmf(zp.z)) * tanhf(hp.z);
    r.w = (1.f - sigmf(zp.w)) * tanhf(hp.w);
    st4split(hh + idx, hl + idx, r);
}

__global__ void e1_kernel(const float* __restrict__ pre,
                          const half* __restrict__ hph, const half* __restrict__ hpl,
                          float* __restrict__ zb,
                          half* __restrict__ rhh, half* __restrict__ rhl, int total4)
{
    int q = blockIdx.x * blockDim.x + threadIdx.x;
    if (q >= total4) return;
    int idx = q * 4;
    int m = idx >> 10, j = idx & 1023;
    size_t o = (size_t)m * 2048 + j;
    float4 zp = *(const float4*)(pre + o);
    float4 rp = *(const float4*)(pre + o + 1024);
    float4 Hh = ld4h(hph + o),        Lh = ld4h(hpl + o);
    float4 Hr = ld4h(hph + o + 1024), Lr = ld4h(hpl + o + 1024);
    float hlx = Hh.x + Lh.x, hly = Hh.y + Lh.y, hlz = Hh.z + Lh.z, hlw = Hh.w + Lh.w;
    float hrx = Hr.x + Lr.x, hry = Hr.y + Lr.y, hrz = Hr.z + Lr.z, hrw = Hr.w + Lr.w;
    float4 z;
    z.x = sigmf(zp.x); z.y = sigmf(zp.y); z.z = sigmf(zp.z); z.w = sigmf(zp.w);
    float rx = sigmf(rp.x), ry = sigmf(rp.y), rz = sigmf(rp.z), rw = sigmf(rp.w);
    *(float4*)(zb + idx) = z;
    st4split(rhh + o,        rhl + o,        make_float4(rx * hlx, ry * hly, rz * hlz, rw * hlw));
    st4split(rhh + o + 1024, rhl + o + 1024, make_float4(rx * hrx, ry * hry, rz * hrz, rw * hrw));
}

template<bool FINAL>
__global__ void e2_kernel(const float* __restrict__ pre2, const float* __restrict__ zb,
                          const half* __restrict__ hph, const half* __restrict__ hpl,
                          half* __restrict__ hoh, half* __restrict__ hol,
                          float* __restrict__ outf, int total4)
{
    int q = blockIdx.x * blockDim.x + threadIdx.x;
    if (q >= total4) return;
    int idx = q * 4;
    int m = idx >> 10, j = idx & 1023;
    size_t o = (size_t)m * 2048 + j;
    float4 z  = *(const float4*)(zb + idx);
    float4 p  = *(const float4*)(pre2 + idx);
    float4 Hh = ld4h(hph + o),        Lh = ld4h(hpl + o);
    float4 Hr = ld4h(hph + o + 1024), Lr = ld4h(hpl + o + 1024);
    float4 r;
    r.x = z.x * ((Hh.x + Lh.x) + (Hr.x + Lr.x)) + (1.f - z.x) * tanhf(p.x);
    r.y = z.y * ((Hh.y + Lh.y) + (Hr.y + Lr.y)) + (1.f - z.y) * tanhf(p.y);
    r.z = z.z * ((Hh.z + Lh.z) + (Hr.z + Lr.z)) + (1.f - z.z) * tanhf(p.z);
    r.w = z.w * ((Hh.w + Lh.w) + (Hr.w + Lr.w)) + (1.f - z.w) * tanhf(p.w);
    if (FINAL) *(float4*)(outf + idx) = r;
    else       st4split(hoh + idx, hol + idx, r);
}

// ================= launch =================
extern "C" void kernel_launch(void* const* d_in, const int* in_sizes, int n_in,
                              void* d_out, int out_size)
{
    const int*   tokens = (const int*)  d_in[0];
    const float* emb    = (const float*)d_in[1];

    PackArgs pa;
    pa.emb = emb;
    pa.Wz  = (const float*)d_in[2];
    pa.bz  = (const float*)d_in[3];
    pa.Uzl = (const float*)d_in[4];
    pa.bzl = (const float*)d_in[5];
    pa.Uzr = (const float*)d_in[6];
    pa.bzr = (const float*)d_in[7];
    pa.br  = (const float*)d_in[9];
    pa.Url = (const float*)d_in[10];
    pa.brl = (const float*)d_in[11];
    pa.Urr = (const float*)d_in[12];
    pa.brr = (const float*)d_in[13];
    pa.Wh  = (const float*)d_in[14];
    pa.bh  = (const float*)d_in[15];
    pa.Uhl = (const float*)d_in[16];
    pa.bhl = (const float*)d_in[17];
    pa.Uhr = (const float*)d_in[18];
    pa.bhr = (const float*)d_in[19];

    half *EMBh, *EMBl, *HB0h, *HB0l, *HB1h, *HB1l, *RHh, *RHl;
    half *W0h, *W0l, *UZRh, *UZRl, *UHh, *UHl;
    float *PRE, *ZB, *BL0, *BZR, *BH;
    cudaGetSymbolAddress((void**)&EMBh, g_EMBh);
    cudaGetSymbolAddress((void**)&EMBl, g_EMBl);
    cudaGetSymbolAddress((void**)&HB0h, g_HB0h);
    cudaGetSymbolAddress((void**)&HB0l, g_HB0l);
    cudaGetSymbolAddress((void**)&HB1h, g_HB1h);
    cudaGetSymbolAddress((void**)&HB1l, g_HB1l);
    cudaGetSymbolAddress((void**)&RHh,  g_RHh);
    cudaGetSymbolAddress((void**)&RHl,  g_RHl);
    cudaGetSymbolAddress((void**)&W0h,  g_W0h);
    cudaGetSymbolAddress((void**)&W0l,  g_W0l);
    cudaGetSymbolAddress((void**)&UZRh, g_UZRh);
    cudaGetSymbolAddress((void**)&UZRl, g_UZRl);
    cudaGetSymbolAddress((void**)&UHh,  g_UHh);
    cudaGetSymbolAddress((void**)&UHl,  g_UHl);
    cudaGetSymbolAddress((void**)&PRE,  g_PRE);
    cudaGetSymbolAddress((void**)&ZB,   g_Z);
    cudaGetSymbolAddress((void**)&BL0,  g_BL0);
    cudaGetSymbolAddress((void**)&BZR,  g_BZR);
    cudaGetSymbolAddress((void**)&BH,   g_BH);

    cudaFuncSetAttribute(gemm_mma_kernel<true>,
                         cudaFuncAttributeMaxDynamicSharedMemorySize, SMEM_BYTES);
    cudaFuncSetAttribute(gemm_mma_kernel<false>,
                         cudaFuncAttributeMaxDynamicSharedMemorySize, SMEM_BYTES);

    // ---- launch 0: megapack (everything) ----
    {
        int nblocks = NB_EMB + 2 * NB_W + 4 + 6 * NB_U;
        megapack_kernel<<<nblocks, 256>>>(pa);
    }

    // ---- launch 1: level-0 GEMM ; launch 2: e0 ----
    {
        dim3 grid(2 * HDIM / BN, M0 / BM);
        gemm_mma_kernel<true><<<grid, 128, SMEM_BYTES>>>(EMBh, EMBl, tokens, W0h, W0l, BL0, PRE,
                                                         M0, 2 * HDIM, EDIM);
        int total4 = M0 * HDIM / 4;
        e0_kernel<<<(total4 + 255) / 256, 256>>>(PRE, HB0h, HB0l, total4);
    }

    // ---- tree levels (launch 3 = level-1 GEMM1, the ncu target) ----
    half* hph = HB0h; half* hpl = HB0l;
    int n = SEQ, lvl = 0;
    while (n > 1) {
        int Mn = BATCH * (n / 2);
        bool final = (n / 2 == 1);
        half* hoh = (lvl & 1) ? HB0h : HB1h;
        half* hol = (lvl & 1) ? HB0l : HB1l;
        int gy = Mn / BM;
        int total4 = Mn * HDIM / 4;

        // GEMM1: [hl|hr](Mn x 2048) @ UZR + [bz|br]
        {
            dim3 grid(2 * HDIM / BN, gy);
            gemm_mma_kernel<false><<<grid, 128, SMEM_BYTES>>>(hph, hpl, nullptr, UZRh, UZRl, BZR, PRE,
                                                              Mn, 2 * HDIM, 2 * HDIM);
        }
        e1_kernel<<<(total4 + 255) / 256, 256>>>(PRE, hph, hpl, ZB, RHh, RHl, total4);
        // GEMM2: [r*hl|r*hr](Mn x 2048) @ UH + bh
        {
            dim3 grid(HDIM / BN, gy);
            gemm_mma_kernel<false><<<grid, 128, SMEM_BYTES>>>(RHh, RHl, nullptr, UHh, UHl, BH, PRE,
                                                              Mn, HDIM, 2 * HDIM);
        }
        if (final)
            e2_kernel<true><<<(total4 + 255) / 256, 256>>>(PRE, ZB, hph, hpl, nullptr, nullptr,
                                                           (float*)d_out, total4);
        else
            e2_kernel<false><<<(total4 + 255) / 256, 256>>>(PRE, ZB, hph, hpl, hoh, hol,
                                                            nullptr, total4);

        hph = hoh; hpl = hol;
        n /= 2;
        lvl++;
    }
    (void)in_sizes; (void)n_in; (void)out_size;
}

// round 12
// speedup vs baseline: 1.5846x; 1.4994x over previous
#include <cuda_runtime.h>
#include <cuda_fp16.h>
#include <math.h>
#include <stdint.h>

// ---------------- problem constants ----------------
#define BATCH   64
#define SEQ     512
#define EDIM    512
#define HDIM    1024
#define VOCAB   32000
#define M0      (BATCH*SEQ)      // 32768 level-0 nodes

// ---------------- device scratch (allocation-free rule) ----------------
__device__ half  g_EMBh[(size_t)VOCAB * EDIM];
__device__ half  g_EMBl[(size_t)VOCAB * EDIM];
__device__ half  g_HB0h[(size_t)M0 * HDIM];
__device__ half  g_HB0l[(size_t)M0 * HDIM];
__device__ half  g_HB1h[(size_t)(M0/2) * HDIM];
__device__ half  g_HB1l[(size_t)(M0/2) * HDIM];
__device__ half  g_RHh [(size_t)(M0/2) * 2 * HDIM];
__device__ half  g_RHl [(size_t)(M0/2) * 2 * HDIM];
__device__ half  g_W0h [(size_t)(2*HDIM) * EDIM];      // [2048][512]  K-major
__device__ half  g_W0l [(size_t)(2*HDIM) * EDIM];
__device__ half  g_UZRh[(size_t)(2*HDIM) * (2*HDIM)];  // [2048][2048]
__device__ half  g_UZRl[(size_t)(2*HDIM) * (2*HDIM)];
__device__ half  g_UHh [(size_t)HDIM * (2*HDIM)];      // [1024][2048]
__device__ half  g_UHl [(size_t)HDIM * (2*HDIM)];
__device__ float g_PRE[(size_t)M0 * 2 * HDIM];
__device__ float g_Z  [(size_t)(M0/2) * HDIM];
__device__ float g_BL0[2*HDIM];
__device__ float g_BZR[2*HDIM];
__device__ float g_BH [HDIM];

// ================= helpers =================
__device__ __forceinline__ uint32_t smem_u32(const void* p) {
    uint32_t a;
    asm("{ .reg .u64 t; cvta.to.shared.u64 t, %1; cvt.u32.u64 %0, t; }" : "=r"(a) : "l"(p));
    return a;
}
__device__ __forceinline__ void split1(float v, half& h, half& l) {
    h = __float2half_rn(v);
    l = __float2half_rn(v - __half2float(h));
}
__device__ __forceinline__ float4 ld4h(const half* p) {
    uint2 u = *(const uint2*)p;
    __half2 a = *(__half2*)&u.x, b = *(__half2*)&u.y;
    float2 fa = __half22float2(a), fb = __half22float2(b);
    return make_float4(fa.x, fa.y, fb.x, fb.y);
}
__device__ __forceinline__ void st4split(half* ph, half* pl, float4 v) {
    half h0, l0, h1, l1, h2, l2, h3, l3;
    split1(v.x, h0, l0); split1(v.y, h1, l1);
    split1(v.z, h2, l2); split1(v.w, h3, l3);
    __half2 H0 = __halves2half2(h0, h1), H1 = __halves2half2(h2, h3);
    __half2 L0 = __halves2half2(l0, l1), L1 = __halves2half2(l2, l3);
    uint2 uh, ul;
    uh.x = *(uint32_t*)&H0; uh.y = *(uint32_t*)&H1;
    ul.x = *(uint32_t*)&L0; ul.y = *(uint32_t*)&L1;
    *(uint2*)ph = uh; *(uint2*)pl = ul;
}

#define CP16(dst, src) asm volatile("cp.async.cg.shared.global [%0], [%1], 16;" :: "r"(dst), "l"(src))
#define CP_COMMIT()    asm volatile("cp.async.commit_group;" ::: "memory")
#define CP_WAIT(n)     asm volatile("cp.async.wait_group %0;" :: "n"(n) : "memory")

#define LDSM4(r0, r1, r2, r3, addr)                                              \
    asm volatile("ldmatrix.sync.aligned.m8n8.x4.shared.b16 {%0,%1,%2,%3}, [%4];" \
        : "=r"(r0), "=r"(r1), "=r"(r2), "=r"(r3) : "r"(addr))

#define MMA16816(d, a, b0, b1)                                                   \
    asm volatile("mma.sync.aligned.m16n8k16.row.col.f32.f16.f16.f32 "            \
        "{%0,%1,%2,%3}, {%4,%5,%6,%7}, {%8,%9}, {%0,%1,%2,%3};"                  \
        : "+f"((d)[0]), "+f"((d)[1]), "+f"((d)[2]), "+f"((d)[3])                  \
        : "r"((a)[0]), "r"((a)[1]), "r"((a)[2]), "r"((a)[3]), "r"(b0), "r"(b1))

__device__ __forceinline__ float sigmf(float x) { return 1.f / (1.f + expf(-x)); }

// ================= megapack =================
#define NB_EMB   16000
#define NB_W     512
#define NB_U     1024

struct PackArgs {
    const float *emb, *Wz, *Wh, *Uzl, *Url, *Uzr, *Urr, *Uhl, *Uhr;
    const float *bz, *bzl, *bzr, *br, *brl, *brr, *bh, *bhl, *bhr;
};

__device__ void do_transpose_split(const float* __restrict__ src,
                                   half* __restrict__ dh, half* __restrict__ dl,
                                   int R, int C, int dpitch, int blk, int tid)
{
    __shared__ float t[32][33];
    int gx = C / 32;
    int c0 = (blk % gx) * 32, r0 = (blk / gx) * 32;
    int x = tid & 31, y = tid >> 5;   // 32 x 8
    #pragma unroll
    for (int i = 0; i < 32; i += 8) {
        t[y + i][x] = src[(size_t)(r0 + y + i) * C + (c0 + x)];
    }
    __syncthreads();
    #pragma unroll
    for (int i = 0; i < 32; i += 8) {
        int c = c0 + y + i, r = r0 + x;
        float v = t[x][y + i];
        half h, l; split1(v, h, l);
        dh[(size_t)c * dpitch + r] = h;
        dl[(size_t)c * dpitch + r] = l;
    }
}

__global__ void __launch_bounds__(256) megapack_kernel(PackArgs a)
{
    const int tid = threadIdx.x;
    int blk = blockIdx.x;

    if (blk < NB_EMB) {
        int q = blk * 256 + tid;
        const int total4 = VOCAB * EDIM / 4;
        if (q < total4) {
            int idx = q * 4;
            float4 v = *(const float4*)(a.emb + idx);
            st4split(g_EMBh + idx, g_EMBl + idx, v);
        }
        return;
    }
    blk -= NB_EMB;
    if (blk < 2 * NB_W) {
        if (blk < NB_W) do_transpose_split(a.Wz, g_W0h, g_W0l, 512, 1024, 512, blk, tid);
        else            do_transpose_split(a.Wh, g_W0h + (size_t)1024*512, g_W0l + (size_t)1024*512,
                                           512, 1024, 512, blk - NB_W, tid);
        return;
    }
    blk -= 2 * NB_W;
    if (blk < 4) {
        int i = blk * 256 + tid;
        float bzs = a.bz[i] + a.bzl[i] + a.bzr[i];
        float brs = a.br[i] + a.brl[i] + a.brr[i];
        float bhs = a.bh[i] + a.bhl[i] + a.bhr[i];
        g_BZR[i] = bzs; g_BZR[1024 + i] = brs;
        g_BH[i]  = bhs;
        g_BL0[i] = bzs; g_BL0[1024 + i] = bhs;
        return;
    }
    blk -= 4;
    {
        int which = blk / NB_U, b = blk % NB_U;
        switch (which) {
            case 0: do_transpose_split(a.Uzl, g_UZRh, g_UZRl, 1024, 1024, 2048, b, tid); break;
            case 1: do_transpose_split(a.Url, g_UZRh + (size_t)1024*2048, g_UZRl + (size_t)1024*2048,
                                       1024, 1024, 2048, b, tid); break;
            case 2: do_transpose_split(a.Uzr, g_UZRh + 1024, g_UZRl + 1024, 1024, 1024, 2048, b, tid); break;
            case 3: do_transpose_split(a.Urr, g_UZRh + (size_t)1024*2048 + 1024,
                                       g_UZRl + (size_t)1024*2048 + 1024, 1024, 1024, 2048, b, tid); break;
            case 4: do_transpose_split(a.Uhl, g_UHh, g_UHl, 1024, 1024, 2048, b, tid); break;
            default: do_transpose_split(a.Uhr, g_UHh + 1024, g_UHl + 1024, 1024, 1024, 2048, b, tid); break;
        }
    }
}

// ================= mma GEMM, cp.async 3-stage =================
// PREC=3: C = (Ah+Al)@(Bh+Bl)^T + bias  (3 MMA terms, drop Al*Bl). 2 CTAs/SM.
// PREC=1: C = Ah@Bh^T + bias            (1 MMA term, gates only).   4 CTAs/SM.
// BM=64, BN=128, BK=32. 4 warps: 2m x 2n, warp tile 32x64.
#define BM 64
#define BN 128
#define BK 32
#define PAD_B 80
#define NSTAGE 3

template<int PREC>
struct GemmCfg {
    static constexpr int oAH = 0;
    static constexpr int oAL = 64 * PAD_B;                      // 5120 (PREC3 only)
    static constexpr int oBH = (PREC == 3) ? (2 * 64 * PAD_B) : (64 * PAD_B);
    static constexpr int oBL = (PREC == 3) ? (2 * 64 * PAD_B + 128 * PAD_B) : 0;
    static constexpr int stage = (PREC == 3) ? (2 * 64 * PAD_B + 2 * 128 * PAD_B)
                                             : (64 * PAD_B + 128 * PAD_B);       // 30720 / 15360
    static constexpr int smem = NSTAGE * stage;                  // 92160 / 46080
    static constexpr int nld  = (PREC == 3) ? 12 : 6;
    static constexpr int occ  = (PREC == 3) ? 2 : 4;
};

template<int PREC, bool GATHER>
__global__ void __launch_bounds__(128, GemmCfg<PREC>::occ)
gemm_mma_kernel(const half* __restrict__ Ah, const half* __restrict__ Al,
                const int* __restrict__ tok,
                const half* __restrict__ Bh, const half* __restrict__ Bl,
                const float* __restrict__ bias,
                float* __restrict__ C, int M, int N, int K)
{
    using Cfg = GemmCfg<PREC>;
    extern __shared__ char smem[];
    const uint32_t sb = smem_u32(smem);
    const int tid  = threadIdx.x;
    const int lane = tid & 31;
    const int wid  = tid >> 5;
    const int warp_m = wid & 1;
    const int warp_n = wid >> 1;
    const int bm = blockIdx.y * BM, bn = blockIdx.x * BN;

    const int r0  = tid >> 2;
    const int seg = (tid & 3) * 16;
    const char* srcp[Cfg::nld];
    uint32_t    dsto[Cfg::nld];
    #pragma unroll
    for (int i = 0; i < Cfg::nld; i++) {
        if (PREC == 3) {
            if (i < 4) {
                int rl = r0 + 32 * (i & 1);
                int gr = bm + rl;
                size_t ar = GATHER ? (size_t)__ldg(&tok[gr]) : (size_t)gr;
                const half* base = (i < 2) ? Ah : Al;
                srcp[i] = (const char*)(base + ar * K) + seg;
                dsto[i] = ((i < 2) ? Cfg::oAH : Cfg::oAL) + (uint32_t)(rl * PAD_B + seg);
            } else {
                int j  = (i - 4) & 3;
                int rl = r0 + 32 * j;
                const half* base = (i < 8) ? Bh : Bl;
                srcp[i] = (const char*)(base + (size_t)(bn + rl) * K) + seg;
                dsto[i] = ((i < 8) ? Cfg::oBH : Cfg::oBL) + (uint32_t)(rl * PAD_B + seg);
            }
        } else {
            if (i < 2) {
                int rl = r0 + 32 * i;
                int gr = bm + rl;
                size_t ar = GATHER ? (size_t)__ldg(&tok[gr]) : (size_t)gr;
                srcp[i] = (const char*)(Ah + ar * K) + seg;
                dsto[i] = Cfg::oAH + (uint32_t)(rl * PAD_B + seg);
            } else {
                int rl = r0 + 32 * (i - 2);
                srcp[i] = (const char*)(Bh + (size_t)(bn + rl) * K) + seg;
                dsto[i] = Cfg::oBH + (uint32_t)(rl * PAD_B + seg);
            }
        }
    }

    const int NT = K / BK;
    auto issue = [&](int kt) {
        if (kt < NT) {
            const uint32_t d = sb + (kt % NSTAGE) * Cfg::stage;
            const size_t g = (size_t)kt * 64;
            #pragma unroll
            for (int i = 0; i < Cfg::nld; i++) CP16(d + dsto[i], srcp[i] + g);
        }
        CP_COMMIT();
    };

    const uint32_t a_lane_off = (uint32_t)((warp_m * 32 + (lane & 15)) * PAD_B + ((lane >> 4) * 8) * 2);
    const uint32_t b_lane_off = (uint32_t)((warp_n * 64 + ((lane >> 4) << 3) + (lane & 7)) * PAD_B
                                           + (((lane >> 3) & 1) * 8) * 2);

    float acc[2][8][4];
    #pragma unroll
    for (int mt = 0; mt < 2; mt++)
        #pragma unroll
        for (int t = 0; t < 8; t++)
            #pragma unroll
            for (int j = 0; j < 4; j++) acc[mt][t][j] = 0.f;

    issue(0);
    issue(1);

    for (int kt = 0; kt < NT; kt++) {
        CP_WAIT(1);
        __syncthreads();
        issue(kt + 2);

        const uint32_t sbase = sb + (kt % NSTAGE) * Cfg::stage;
        #pragma unroll
        for (int ks = 0; ks < 2; ks++) {
            const uint32_t koff = ks * 32;
            uint32_t ah[2][4], al[2][4], bh[4][4], bl[4][4];
            #pragma unroll
            for (int mt = 0; mt < 2; mt++) {
                uint32_t ad = sbase + a_lane_off + mt * (16 * PAD_B) + koff;
                LDSM4(ah[mt][0], ah[mt][1], ah[mt][2], ah[mt][3], ad + Cfg::oAH);
                if (PREC == 3) LDSM4(al[mt][0], al[mt][1], al[mt][2], al[mt][3], ad + Cfg::oAL);
            }
            #pragma unroll
            for (int ng = 0; ng < 4; ng++) {
                uint32_t bd = sbase + b_lane_off + ng * (16 * PAD_B) + koff;
                LDSM4(bh[ng][0], bh[ng][1], bh[ng][2], bh[ng][3], bd + Cfg::oBH);
                if (PREC == 3) LDSM4(bl[ng][0], bl[ng][1], bl[ng][2], bl[ng][3], bd + Cfg::oBL);
            }
            #pragma unroll
            for (int mt = 0; mt < 2; mt++)
                #pragma unroll
                for (int ng = 0; ng < 4; ng++)
                    #pragma unroll
                    for (int p = 0; p < 2; p++) {
                        float* c = acc[mt][ng * 2 + p];
                        MMA16816(c, ah[mt], bh[ng][2 * p], bh[ng][2 * p + 1]);
                        if (PREC == 3) {
                            MMA16816(c, ah[mt], bl[ng][2 * p], bl[ng][2 * p + 1]);
                            MMA16816(c, al[mt], bh[ng][2 * p], bh[ng][2 * p + 1]);
                        }
                    }
        }
    }

    const int r0e = bm + warp_m * 32 + (lane >> 2);
    const int c0e = bn + warp_n * 64 + (lane & 3) * 2;
    #pragma unroll
    for (int mt = 0; mt < 2; mt++) {
        const int row = r0e + mt * 16;
        #pragma unroll
        for (int t = 0; t < 8; t++) {
            const int col = c0e + t * 8;
            const float b0 = bias[col], b1 = bias[col + 1];
            float2 v0 = make_float2(acc[mt][t][0] + b0, acc[mt][t][1] + b1);
            *(float2*)(C + (size_t)row * N + col) = v0;
            float2 v1 = make_float2(acc[mt][t][2] + b0, acc[mt][t][3] + b1);
            *(float2*)(C + (size_t)(row + 8) * N + col) = v1;
        }
    }
}

// ================= elementwise epilogues =================
__global__ void e0_kernel(const float* __restrict__ pre,
                          half* __restrict__ hh, half* __restrict__ hl, int total4)
{
    int q = blockIdx.x * blockDim.x + threadIdx.x;
    if (q >= total4) return;
    int idx = q * 4;
    int m = idx >> 10, j = idx & 1023;
    size_t o = (size_t)m * 2048 + j;
    float4 zp = *(const float4*)(pre + o);
    float4 hp = *(const float4*)(pre + o + 1024);
    float4 r;
    r.x = (1.f - sigmf(zp.x)) * tanhf(hp.x);
    r.y = (1.f - sigmf(zp.y)) * tanhf(hp.y);
    r.z = (1.f - sigmf(zp.z)) * tanhf(hp.z);
    r.w = (1.f - sigmf(zp.w)) * tanhf(hp.w);
    st4split(hh + idx, hl + idx, r);
}

__global__ void e1_kernel(const float* __restrict__ pre,
                          const half* __restrict__ hph, const half* __restrict__ hpl,
                          float* __restrict__ zb,
                          half* __restrict__ rhh, half* __restrict__ rhl, int total4)
{
    int q = blockIdx.x * blockDim.x + threadIdx.x;
    if (q >= total4) return;
    int idx = q * 4;
    int m = idx >> 10, j = idx & 1023;
    size_t o = (size_t)m * 2048 + j;
    float4 zp = *(const float4*)(pre + o);
    float4 rp = *(const float4*)(pre + o + 1024);
    float4 Hh = ld4h(hph + o),        Lh = ld4h(hpl + o);
    float4 Hr = ld4h(hph + o + 1024), Lr = ld4h(hpl + o + 1024);
    float hlx = Hh.x + Lh.x, hly = Hh.y + Lh.y, hlz = Hh.z + Lh.z, hlw = Hh.w + Lh.w;
    float hrx = Hr.x + Lr.x, hry = Hr.y + Lr.y, hrz = Hr.z + Lr.z, hrw = Hr.w + Lr.w;
    float4 z;
    z.x = sigmf(zp.x); z.y = sigmf(zp.y); z.z = sigmf(zp.z); z.w = sigmf(zp.w);
    float rx = sigmf(rp.x), ry = sigmf(rp.y), rz = sigmf(rp.z), rw = sigmf(rp.w);
    *(float4*)(zb + idx) = z;
    st4split(rhh + o,        rhl + o,        make_float4(rx * hlx, ry * hly, rz * hlz, rw * hlw));
    st4split(rhh + o + 1024, rhl + o + 1024, make_float4(rx * hrx, ry * hry, rz * hrz, rw * hrw));
}

template<bool FINAL>
__global__ void e2_kernel(const float* __restrict__ pre2, const float* __restrict__ zb,
                          const half* __restrict__ hph, const half* __restrict__ hpl,
                          half* __restrict__ hoh, half* __restrict__ hol,
                          float* __restrict__ outf, int total4)
{
    int q = blockIdx.x * blockDim.x + threadIdx.x;
    if (q >= total4) return;
    int idx = q * 4;
    int m = idx >> 10, j = idx & 1023;
    size_t o = (size_t)m * 2048 + j;
    float4 z  = *(const float4*)(zb + idx);
    float4 p  = *(const float4*)(pre2 + idx);
    float4 Hh = ld4h(hph + o),        Lh = ld4h(hpl + o);
    float4 Hr = ld4h(hph + o + 1024), Lr = ld4h(hpl + o + 1024);
    float4 r;
    r.x = z.x * ((Hh.x + Lh.x) + (Hr.x + Lr.x)) + (1.f - z.x) * tanhf(p.x);
    r.y = z.y * ((Hh.y + Lh.y) + (Hr.y + Lr.y)) + (1.f - z.y) * tanhf(p.y);
    r.z = z.z * ((Hh.z + Lh.z) + (Hr.z + Lr.z)) + (1.f - z.z) * tanhf(p.z);
    r.w = z.w * ((Hh.w + Lh.w) + (Hr.w + Lr.w)) + (1.f - z.w) * tanhf(p.w);
    if (FINAL) *(float4*)(outf + idx) = r;
    else       st4split(hoh + idx, hol + idx, r);
}

// ================= launch =================
extern "C" void kernel_launch(void* const* d_in, const int* in_sizes, int n_in,
                              void* d_out, int out_size)
{
    const int*   tokens = (const int*)  d_in[0];
    const float* emb    = (const float*)d_in[1];

    PackArgs pa;
    pa.emb = emb;
    pa.Wz  = (const float*)d_in[2];
    pa.bz  = (const float*)d_in[3];
    pa.Uzl = (const float*)d_in[4];
    pa.bzl = (const float*)d_in[5];
    pa.Uzr = (const float*)d_in[6];
    pa.bzr = (const float*)d_in[7];
    pa.br  = (const float*)d_in[9];
    pa.Url = (const float*)d_in[10];
    pa.brl = (const float*)d_in[11];
    pa.Urr = (const float*)d_in[12];
    pa.brr = (const float*)d_in[13];
    pa.Wh  = (const float*)d_in[14];
    pa.bh  = (const float*)d_in[15];
    pa.Uhl = (const float*)d_in[16];
    pa.bhl = (const float*)d_in[17];
    pa.Uhr = (const float*)d_in[18];
    pa.bhr = (const float*)d_in[19];

    half *EMBh, *EMBl, *HB0h, *HB0l, *HB1h, *HB1l, *RHh, *RHl;
    half *W0h, *W0l, *UZRh, *UZRl, *UHh, *UHl;
    float *PRE, *ZB, *BL0, *BZR, *BH;
    cudaGetSymbolAddress((void**)&EMBh, g_EMBh);
    cudaGetSymbolAddress((void**)&EMBl, g_EMBl);
    cudaGetSymbolAddress((void**)&HB0h, g_HB0h);
    cudaGetSymbolAddress((void**)&HB0l, g_HB0l);
    cudaGetSymbolAddress((void**)&HB1h, g_HB1h);
    cudaGetSymbolAddress((void**)&HB1l, g_HB1l);
    cudaGetSymbolAddress((void**)&RHh,  g_RHh);
    cudaGetSymbolAddress((void**)&RHl,  g_RHl);
    cudaGetSymbolAddress((void**)&W0h,  g_W0h);
    cudaGetSymbolAddress((void**)&W0l,  g_W0l);
    cudaGetSymbolAddress((void**)&UZRh, g_UZRh);
    cudaGetSymbolAddress((void**)&UZRl, g_UZRl);
    cudaGetSymbolAddress((void**)&UHh,  g_UHh);
    cudaGetSymbolAddress((void**)&UHl,  g_UHl);
    cudaGetSymbolAddress((void**)&PRE,  g_PRE);
    cudaGetSymbolAddress((void**)&ZB,   g_Z);
    cudaGetSymbolAddress((void**)&BL0,  g_BL0);
    cudaGetSymbolAddress((void**)&BZR,  g_BZR);
    cudaGetSymbolAddress((void**)&BH,   g_BH);

    cudaFuncSetAttribute(gemm_mma_kernel<3, true>,
                         cudaFuncAttributeMaxDynamicSharedMemorySize, GemmCfg<3>::smem);
    cudaFuncSetAttribute(gemm_mma_kernel<3, false>,
                         cudaFuncAttributeMaxDynamicSharedMemorySize, GemmCfg<3>::smem);
    cudaFuncSetAttribute(gemm_mma_kernel<1, false>,
                         cudaFuncAttributeMaxDynamicSharedMemorySize, GemmCfg<1>::smem);

    // ---- launch 0: megapack ----
    {
        int nblocks = NB_EMB + 2 * NB_W + 4 + 6 * NB_U;
        megapack_kernel<<<nblocks, 256>>>(pa);
    }

    // ---- launch 1: level-0 GEMM (full precision) ; launch 2: e0 ----
    {
        dim3 grid(2 * HDIM / BN, M0 / BM);
        gemm_mma_kernel<3, true><<<grid, 128, GemmCfg<3>::smem>>>(
            EMBh, EMBl, tokens, W0h, W0l, BL0, PRE, M0, 2 * HDIM, EDIM);
        int total4 = M0 * HDIM / 4;
        e0_kernel<<<(total4 + 255) / 256, 256>>>(PRE, HB0h, HB0l, total4);
    }

    // ---- tree levels (launch 3 = level-1 GEMM1, the ncu target) ----
    half* hph = HB0h; half* hpl = HB0l;
    int n = SEQ, lvl = 0;
    while (n > 1) {
        int Mn = BATCH * (n / 2);
        bool final = (n / 2 == 1);
        half* hoh = (lvl & 1) ? HB0h : HB1h;
        half* hol = (lvl & 1) ? HB0l : HB1l;
        int gy = Mn / BM;
        int total4 = Mn * HDIM / 4;

        // GEMM1 (gates, PREC=1 hi-only): [hl|hr] @ UZR + [bz|br]
        {
            dim3 grid(2 * HDIM / BN, gy);
            gemm_mma_kernel<1, false><<<grid, 128, GemmCfg<1>::smem>>>(
                hph, nullptr, nullptr, UZRh, nullptr, BZR, PRE, Mn, 2 * HDIM, 2 * HDIM);
        }
        e1_kernel<<<(total4 + 255) / 256, 256>>>(PRE, hph, hpl, ZB, RHh, RHl, total4);
        // GEMM2 (h-tilde, PREC=3): [r*hl|r*hr] @ UH + bh
        {
            dim3 grid(HDIM / BN, gy);
            gemm_mma_kernel<3, false><<<grid, 128, GemmCfg<3>::smem>>>(
                RHh, RHl, nullptr, UHh, UHl, BH, PRE, Mn, HDIM, 2 * HDIM);
        }
        if (final)
            e2_kernel<true><<<(total4 + 255) / 256, 256>>>(PRE, ZB, hph, hpl, nullptr, nullptr,
                                                           (float*)d_out, total4);
        else
            e2_kernel<false><<<(total4 + 255) / 256, 256>>>(PRE, ZB, hph, hpl, hoh, hol,
                                                            nullptr, total4);

        hph = hoh; hpl = hol;
        n /= 2;
        lvl++;
    }
    (void)in_sizes; (void)n_in; (void)out_size;
}

// round 13
// speedup vs baseline: 1.9904x; 1.2561x over previous
#include <cuda_runtime.h>
#include <cuda_fp16.h>
#include <math.h>
#include <stdint.h>

// ---------------- problem constants ----------------
#define BATCH   64
#define SEQ     512
#define EDIM    512
#define HDIM    1024
#define VOCAB   32000
#define M0      (BATCH*SEQ)      // 32768 level-0 nodes

// ---------------- device scratch (allocation-free rule) ----------------
__device__ half  g_EMBh[(size_t)VOCAB * EDIM];
__device__ half  g_HB0h[(size_t)M0 * HDIM];
__device__ half  g_HB0l[(size_t)M0 * HDIM];
__device__ half  g_HB1h[(size_t)(M0/2) * HDIM];
__device__ half  g_HB1l[(size_t)(M0/2) * HDIM];
__device__ half  g_RHh [(size_t)(M0/2) * 2 * HDIM];
__device__ half  g_W0h [(size_t)(2*HDIM) * EDIM];      // [2048][512]  K-major
__device__ half  g_W0l [(size_t)(2*HDIM) * EDIM];
__device__ half  g_UZRh[(size_t)(2*HDIM) * (2*HDIM)];  // [2048][2048]
__device__ half  g_UHh [(size_t)HDIM * (2*HDIM)];      // [1024][2048]
__device__ half  g_UHl [(size_t)HDIM * (2*HDIM)];
__device__ float g_PRE[(size_t)M0 * 2 * HDIM];
__device__ float g_Z  [(size_t)(M0/2) * HDIM];
__device__ float g_BL0[2*HDIM];
__device__ float g_BZR[2*HDIM];
__device__ float g_BH [HDIM];

// ================= helpers =================
__device__ __forceinline__ uint32_t smem_u32(const void* p) {
    uint32_t a;
    asm("{ .reg .u64 t; cvta.to.shared.u64 t, %1; cvt.u32.u64 %0, t; }" : "=r"(a) : "l"(p));
    return a;
}
__device__ __forceinline__ void split1(float v, half& h, half& l) {
    h = __float2half_rn(v);
    l = __float2half_rn(v - __half2float(h));
}
__device__ __forceinline__ float4 ld4h(const half* p) {
    uint2 u = *(const uint2*)p;
    __half2 a = *(__half2*)&u.x, b = *(__half2*)&u.y;
    float2 fa = __half22float2(a), fb = __half22float2(b);
    return make_float4(fa.x, fa.y, fb.x, fb.y);
}
__device__ __forceinline__ void st4split(half* ph, half* pl, float4 v) {
    half h0, l0, h1, l1, h2, l2, h3, l3;
    split1(v.x, h0, l0); split1(v.y, h1, l1);
    split1(v.z, h2, l2); split1(v.w, h3, l3);
    __half2 H0 = __halves2half2(h0, h1), H1 = __halves2half2(h2, h3);
    __half2 L0 = __halves2half2(l0, l1), L1 = __halves2half2(l2, l3);
    uint2 uh, ul;
    uh.x = *(uint32_t*)&H0; uh.y = *(uint32_t*)&H1;
    ul.x = *(uint32_t*)&L0; ul.y = *(uint32_t*)&L1;
    *(uint2*)ph = uh; *(uint2*)pl = ul;
}
__device__ __forceinline__ void st4hi(half* ph, float4 v) {
    __half2 a = __floats2half2_rn(v.x, v.y);
    __half2 b = __floats2half2_rn(v.z, v.w);
    uint2 u;
    u.x = *(uint32_t*)&a; u.y = *(uint32_t*)&b;
    *(uint2*)ph = u;
}

#define CP16(dst, src) asm volatile("cp.async.cg.shared.global [%0], [%1], 16;" :: "r"(dst), "l"(src))
#define CP_COMMIT()    asm volatile("cp.async.commit_group;" ::: "memory")
#define CP_WAIT(n)     asm volatile("cp.async.wait_group %0;" :: "n"(n) : "memory")

#define LDSM4(r0, r1, r2, r3, addr)                                              \
    asm volatile("ldmatrix.sync.aligned.m8n8.x4.shared.b16 {%0,%1,%2,%3}, [%4];" \
        : "=r"(r0), "=r"(r1), "=r"(r2), "=r"(r3) : "r"(addr))

#define MMA16816(d, a, b0, b1)                                                   \
    asm volatile("mma.sync.aligned.m16n8k16.row.col.f32.f16.f16.f32 "            \
        "{%0,%1,%2,%3}, {%4,%5,%6,%7}, {%8,%9}, {%0,%1,%2,%3};"                  \
        : "+f"((d)[0]), "+f"((d)[1]), "+f"((d)[2]), "+f"((d)[3])                  \
        : "r"((a)[0]), "r"((a)[1]), "r"((a)[2]), "r"((a)[3]), "r"(b0), "r"(b1))

__device__ __forceinline__ float sigmf(float x) { return 1.f / (1.f + expf(-x)); }

// ================= megapack =================
#define NB_EMB   16000
#define NB_W     512
#define NB_U     1024

struct PackArgs {
    const float *emb, *Wz, *Wh, *Uzl, *Url, *Uzr, *Urr, *Uhl, *Uhr;
    const float *bz, *bzl, *bzr, *br, *brl, *brr, *bh, *bhl, *bhr;
};

__device__ void do_transpose_split(const float* __restrict__ src,
                                   half* __restrict__ dh, half* __restrict__ dl,
                                   int R, int C, int dpitch, int blk, int tid,
                                   bool writeLo)
{
    __shared__ float t[32][33];
    int gx = C / 32;
    int c0 = (blk % gx) * 32, r0 = (blk / gx) * 32;
    int x = tid & 31, y = tid >> 5;   // 32 x 8
    #pragma unroll
    for (int i = 0; i < 32; i += 8) {
        t[y + i][x] = src[(size_t)(r0 + y + i) * C + (c0 + x)];
    }
    __syncthreads();
    #pragma unroll
    for (int i = 0; i < 32; i += 8) {
        int c = c0 + y + i, r = r0 + x;
        float v = t[x][y + i];
        half h, l; split1(v, h, l);
        dh[(size_t)c * dpitch + r] = h;
        if (writeLo) dl[(size_t)c * dpitch + r] = l;
    }
}

__global__ void __launch_bounds__(256) megapack_kernel(PackArgs a)
{
    const int tid = threadIdx.x;
    int blk = blockIdx.x;

    if (blk < NB_EMB) {   // emb -> hi plane only
        int q = blk * 256 + tid;
        const int total4 = VOCAB * EDIM / 4;
        if (q < total4) {
            int idx = q * 4;
            float4 v = *(const float4*)(a.emb + idx);
            st4hi(g_EMBh + idx, v);
        }
        return;
    }
    blk -= NB_EMB;
    if (blk < 2 * NB_W) { // W0 transposes (hi+lo: B operand of level-0 2-term GEMM)
        if (blk < NB_W) do_transpose_split(a.Wz, g_W0h, g_W0l, 512, 1024, 512, blk, tid, true);
        else            do_transpose_split(a.Wh, g_W0h + (size_t)1024*512, g_W0l + (size_t)1024*512,
                                           512, 1024, 512, blk - NB_W, tid, true);
        return;
    }
    blk -= 2 * NB_W;
    if (blk < 4) {
        int i = blk * 256 + tid;
        float bzs = a.bz[i] + a.bzl[i] + a.bzr[i];
        float brs = a.br[i] + a.brl[i] + a.brr[i];
        float bhs = a.bh[i] + a.bhl[i] + a.bhr[i];
        g_BZR[i] = bzs; g_BZR[1024 + i] = brs;
        g_BH[i]  = bhs;
        g_BL0[i] = bzs; g_BL0[1024 + i] = bhs;
        return;
    }
    blk -= 4;
    {
        int which = blk / NB_U, b = blk % NB_U;
        switch (which) {
            // UZR: hi only (PREC1 gate GEMM)
            case 0: do_transpose_split(a.Uzl, g_UZRh, nullptr, 1024, 1024, 2048, b, tid, false); break;
            case 1: do_transpose_split(a.Url, g_UZRh + (size_t)1024*2048, nullptr,
                                       1024, 1024, 2048, b, tid, false); break;
            case 2: do_transpose_split(a.Uzr, g_UZRh + 1024, nullptr, 1024, 1024, 2048, b, tid, false); break;
            case 3: do_transpose_split(a.Urr, g_UZRh + (size_t)1024*2048 + 1024, nullptr,
                                       1024, 1024, 2048, b, tid, false); break;
            // UH: hi+lo (B operand of 2-term GEMM2)
            case 4: do_transpose_split(a.Uhl, g_UHh, g_UHl, 1024, 1024, 2048, b, tid, true); break;
            default: do_transpose_split(a.Uhr, g_UHh + 1024, g_UHl + 1024, 1024, 1024, 2048, b, tid, true); break;
        }
    }
}

// ================= mma GEMM, cp.async 3-stage =================
// BPL = B planes. A is always hi-only.
// BPL=1: C = Ah@Bh^T + bias            (gates).         4 CTAs/SM.
// BPL=2: C = Ah@(Bh+Bl)^T + bias       (level-0, GEMM2). 3 CTAs/SM.
// BM=64, BN=128, BK=32. 4 warps: 2m x 2n, warp tile 32x64.
#define BM 64
#define BN 128
#define BK 32
#define PAD_B 80
#define NSTAGE 3

template<int BPL>
struct GemmCfg {
    static constexpr int oAH   = 0;
    static constexpr int oBH   = 64 * PAD_B;                       // 5120
    static constexpr int oBL   = 64 * PAD_B + 128 * PAD_B;         // 15360 (BPL2)
    static constexpr int stage = (64 + BPL * 128) * PAD_B;         // 15360 / 25600
    static constexpr int smem  = NSTAGE * stage;                   // 46080 / 76800
    static constexpr int nld   = 2 + 4 * BPL;                      // 6 / 10
    static constexpr int occ   = (BPL == 1) ? 4 : 3;
};

template<int BPL, bool GATHER>
__global__ void __launch_bounds__(128, GemmCfg<BPL>::occ)
gemm_mma_kernel(const half* __restrict__ Ah,
                const int* __restrict__ tok,
                const half* __restrict__ Bh, const half* __restrict__ Bl,
                const float* __restrict__ bias,
                float* __restrict__ C, int M, int N, int K)
{
    using Cfg = GemmCfg<BPL>;
    extern __shared__ char smem[];
    const uint32_t sb = smem_u32(smem);
    const int tid  = threadIdx.x;
    const int lane = tid & 31;
    const int wid  = tid >> 5;
    const int warp_m = wid & 1;
    const int warp_n = wid >> 1;
    const int bm = blockIdx.y * BM, bn = blockIdx.x * BN;

    const int r0  = tid >> 2;
    const int seg = (tid & 3) * 16;
    const char* srcp[Cfg::nld];
    uint32_t    dsto[Cfg::nld];
    #pragma unroll
    for (int i = 0; i < Cfg::nld; i++) {
        if (i < 2) {
            int rl = r0 + 32 * i;
            int gr = bm + rl;
            size_t ar = GATHER ? (size_t)__ldg(&tok[gr]) : (size_t)gr;
            srcp[i] = (const char*)(Ah + ar * K) + seg;
            dsto[i] = Cfg::oAH + (uint32_t)(rl * PAD_B + seg);
        } else if (i < 6) {
            int rl = r0 + 32 * (i - 2);
            srcp[i] = (const char*)(Bh + (size_t)(bn + rl) * K) + seg;
            dsto[i] = Cfg::oBH + (uint32_t)(rl * PAD_B + seg);
        } else {
            int rl = r0 + 32 * (i - 6);
            srcp[i] = (const char*)(Bl + (size_t)(bn + rl) * K) + seg;
            dsto[i] = Cfg::oBL + (uint32_t)(rl * PAD_B + seg);
        }
    }

    const int NT = K / BK;
    auto issue = [&](int kt) {
        if (kt < NT) {
            const uint32_t d = sb + (kt % NSTAGE) * Cfg::stage;
            const size_t g = (size_t)kt * 64;
            #pragma unroll
            for (int i = 0; i < Cfg::nld; i++) CP16(d + dsto[i], srcp[i] + g);
        }
        CP_COMMIT();
    };

    const uint32_t a_lane_off = (uint32_t)((warp_m * 32 + (lane & 15)) * PAD_B + ((lane >> 4) * 8) * 2);
    const uint32_t b_lane_off = (uint32_t)((warp_n * 64 + ((lane >> 4) << 3) + (lane & 7)) * PAD_B
                                           + (((lane >> 3) & 1) * 8) * 2);

    float acc[2][8][4];
    #pragma unroll
    for (int mt = 0; mt < 2; mt++)
        #pragma unroll
        for (int t = 0; t < 8; t++)
            #pragma unroll
            for (int j = 0; j < 4; j++) acc[mt][t][j] = 0.f;

    issue(0);
    issue(1);

    for (int kt = 0; kt < NT; kt++) {
        CP_WAIT(1);
        __syncthreads();
        issue(kt + 2);

        const uint32_t sbase = sb + (kt % NSTAGE) * Cfg::stage;
        #pragma unroll
        for (int ks = 0; ks < 2; ks++) {
            const uint32_t koff = ks * 32;
            uint32_t ah[2][4], bh[4][4], bl[4][4];
            #pragma unroll
            for (int mt = 0; mt < 2; mt++) {
                uint32_t ad = sbase + a_lane_off + mt * (16 * PAD_B) + koff;
                LDSM4(ah[mt][0], ah[mt][1], ah[mt][2], ah[mt][3], ad + Cfg::oAH);
            }
            #pragma unroll
            for (int ng = 0; ng < 4; ng++) {
                uint32_t bd = sbase + b_lane_off + ng * (16 * PAD_B) + koff;
                LDSM4(bh[ng][0], bh[ng][1], bh[ng][2], bh[ng][3], bd + Cfg::oBH);
                if (BPL == 2) LDSM4(bl[ng][0], bl[ng][1], bl[ng][2], bl[ng][3], bd + Cfg::oBL);
            }
            #pragma unroll
            for (int mt = 0; mt < 2; mt++)
                #pragma unroll
                for (int ng = 0; ng < 4; ng++)
                    #pragma unroll
                    for (int p = 0; p < 2; p++) {
                        float* c = acc[mt][ng * 2 + p];
                        MMA16816(c, ah[mt], bh[ng][2 * p], bh[ng][2 * p + 1]);
                        if (BPL == 2)
                            MMA16816(c, ah[mt], bl[ng][2 * p], bl[ng][2 * p + 1]);
                    }
        }
    }

    const int r0e = bm + warp_m * 32 + (lane >> 2);
    const int c0e = bn + warp_n * 64 + (lane & 3) * 2;
    #pragma unroll
    for (int mt = 0; mt < 2; mt++) {
        const int row = r0e + mt * 16;
        #pragma unroll
        for (int t = 0; t < 8; t++) {
            const int col = c0e + t * 8;
            const float b0 = bias[col], b1 = bias[col + 1];
            float2 v0 = make_float2(acc[mt][t][0] + b0, acc[mt][t][1] + b1);
            *(float2*)(C + (size_t)row * N + col) = v0;
            float2 v1 = make_float2(acc[mt][t][2] + b0, acc[mt][t][3] + b1);
            *(float2*)(C + (size_t)(row + 8) * N + col) = v1;
        }
    }
}

// ================= elementwise epilogues =================
__global__ void e0_kernel(const float* __restrict__ pre,
                          half* __restrict__ hh, half* __restrict__ hl, int total4)
{
    int q = blockIdx.x * blockDim.x + threadIdx.x;
    if (q >= total4) return;
    int idx = q * 4;
    int m = idx >> 10, j = idx & 1023;
    size_t o = (size_t)m * 2048 + j;
    float4 zp = *(const float4*)(pre + o);
    float4 hp = *(const float4*)(pre + o + 1024);
    float4 r;
    r.x = (1.f - sigmf(zp.x)) * tanhf(hp.x);
    r.y = (1.f - sigmf(zp.y)) * tanhf(hp.y);
    r.z = (1.f - sigmf(zp.z)) * tanhf(hp.z);
    r.w = (1.f - sigmf(zp.w)) * tanhf(hp.w);
    st4split(hh + idx, hl + idx, r);
}

// after GEMM1: pre = [zpre | rpre]; writes z (fp32) and r*h hi-plane only
__global__ void e1_kernel(const float* __restrict__ pre,
                          const half* __restrict__ hph, const half* __restrict__ hpl,
                          float* __restrict__ zb,
                          half* __restrict__ rhh, int total4)
{
    int q = blockIdx.x * blockDim.x + threadIdx.x;
    if (q >= total4) return;
    int idx = q * 4;
    int m = idx >> 10, j = idx & 1023;
    size_t o = (size_t)m * 2048 + j;
    float4 zp = *(const float4*)(pre + o);
    float4 rp = *(const float4*)(pre + o + 1024);
    float4 Hh = ld4h(hph + o),        Lh = ld4h(hpl + o);
    float4 Hr = ld4h(hph + o + 1024), Lr = ld4h(hpl + o + 1024);
    float hlx = Hh.x + Lh.x, hly = Hh.y + Lh.y, hlz = Hh.z + Lh.z, hlw = Hh.w + Lh.w;
    float hrx = Hr.x + Lr.x, hry = Hr.y + Lr.y, hrz = Hr.z + Lr.z, hrw = Hr.w + Lr.w;
    float4 z;
    z.x = sigmf(zp.x); z.y = sigmf(zp.y); z.z = sigmf(zp.z); z.w = sigmf(zp.w);
    float rx = sigmf(rp.x), ry = sigmf(rp.y), rz = sigmf(rp.z), rw = sigmf(rp.w);
    *(float4*)(zb + idx) = z;
    st4hi(rhh + o,        make_float4(rx * hlx, ry * hly, rz * hlz, rw * hlw));
    st4hi(rhh + o + 1024, make_float4(rx * hrx, ry * hry, rz * hrz, rw * hrw));
}

template<bool FINAL>
__global__ void e2_kernel(const float* __restrict__ pre2, const float* __restrict__ zb,
                          const half* __restrict__ hph, const half* __restrict__ hpl,
                          half* __restrict__ hoh, half* __restrict__ hol,
                          float* __restrict__ outf, int total4)
{
    int q = blockIdx.x * blockDim.x + threadIdx.x;
    if (q >= total4) return;
    int idx = q * 4;
    int m = idx >> 10, j = idx & 1023;
    size_t o = (size_t)m * 2048 + j;
    float4 z  = *(const float4*)(zb + idx);
    float4 p  = *(const float4*)(pre2 + idx);
    float4 Hh = ld4h(hph + o),        Lh = ld4h(hpl + o);
    float4 Hr = ld4h(hph + o + 1024), Lr = ld4h(hpl + o + 1024);
    float4 r;
    r.x = z.x * ((Hh.x + Lh.x) + (Hr.x + Lr.x)) + (1.f - z.x) * tanhf(p.x);
    r.y = z.y * ((Hh.y + Lh.y) + (Hr.y + Lr.y)) + (1.f - z.y) * tanhf(p.y);
    r.z = z.z * ((Hh.z + Lh.z) + (Hr.z + Lr.z)) + (1.f - z.z) * tanhf(p.z);
    r.w = z.w * ((Hh.w + Lh.w) + (Hr.w + Lr.w)) + (1.f - z.w) * tanhf(p.w);
    if (FINAL) *(float4*)(outf + idx) = r;
    else       st4split(hoh + idx, hol + idx, r);
}

// ================= launch =================
extern "C" void kernel_launch(void* const* d_in, const int* in_sizes, int n_in,
                              void* d_out, int out_size)
{
    const int*   tokens = (const int*)  d_in[0];
    const float* emb    = (const float*)d_in[1];

    PackArgs pa;
    pa.emb = emb;
    pa.Wz  = (const float*)d_in[2];
    pa.bz  = (const float*)d_in[3];
    pa.Uzl = (const float*)d_in[4];
    pa.bzl = (const float*)d_in[5];
    pa.Uzr = (const float*)d_in[6];
    pa.bzr = (const float*)d_in[7];
    pa.br  = (const float*)d_in[9];
    pa.Url = (const float*)d_in[10];
    pa.brl = (const float*)d_in[11];
    pa.Urr = (const float*)d_in[12];
    pa.brr = (const float*)d_in[13];
    pa.Wh  = (const float*)d_in[14];
    pa.bh  = (const float*)d_in[15];
    pa.Uhl = (const float*)d_in[16];
    pa.bhl = (const float*)d_in[17];
    pa.Uhr = (const float*)d_in[18];
    pa.bhr = (const float*)d_in[19];

    half *EMBh, *HB0h, *HB0l, *HB1h, *HB1l, *RHh;
    half *W0h, *W0l, *UZRh, *UHh, *UHl;
    float *PRE, *ZB, *BL0, *BZR, *BH;
    cudaGetSymbolAddress((void**)&EMBh, g_EMBh);
    cudaGetSymbolAddress((void**)&HB0h, g_HB0h);
    cudaGetSymbolAddress((void**)&HB0l, g_HB0l);
    cudaGetSymbolAddress((void**)&HB1h, g_HB1h);
    cudaGetSymbolAddress((void**)&HB1l, g_HB1l);
    cudaGetSymbolAddress((void**)&RHh,  g_RHh);
    cudaGetSymbolAddress((void**)&W0h,  g_W0h);
    cudaGetSymbolAddress((void**)&W0l,  g_W0l);
    cudaGetSymbolAddress((void**)&UZRh, g_UZRh);
    cudaGetSymbolAddress((void**)&UHh,  g_UHh);
    cudaGetSymbolAddress((void**)&UHl,  g_UHl);
    cudaGetSymbolAddress((void**)&PRE,  g_PRE);
    cudaGetSymbolAddress((void**)&ZB,   g_Z);
    cudaGetSymbolAddress((void**)&BL0,  g_BL0);
    cudaGetSymbolAddress((void**)&BZR,  g_BZR);
    cudaGetSymbolAddress((void**)&BH,   g_BH);

    cudaFuncSetAttribute(gemm_mma_kernel<2, true>,
                         cudaFuncAttributeMaxDynamicSharedMemorySize, GemmCfg<2>::smem);
    cudaFuncSetAttribute(gemm_mma_kernel<2, false>,
                         cudaFuncAttributeMaxDynamicSharedMemorySize, GemmCfg<2>::smem);
    cudaFuncSetAttribute(gemm_mma_kernel<1, false>,
                         cudaFuncAttributeMaxDynamicSharedMemorySize, GemmCfg<1>::smem);

    // ---- launch 0: megapack ----
    {
        int nblocks = NB_EMB + 2 * NB_W + 4 + 6 * NB_U;
        megapack_kernel<<<nblocks, 256>>>(pa);
    }

    // ---- launch 1: level-0 GEMM (2-term: emb_hi @ (W0h+W0l)) ; launch 2: e0 ----
    {
        dim3 grid(2 * HDIM / BN, M0 / BM);
        gemm_mma_kernel<2, true><<<grid, 128, GemmCfg<2>::smem>>>(
            EMBh, tokens, W0h, W0l, BL0, PRE, M0, 2 * HDIM, EDIM);
        int total4 = M0 * HDIM / 4;
        e0_kernel<<<(total4 + 255) / 256, 256>>>(PRE, HB0h, HB0l, total4);
    }

    // ---- tree levels (launch 3 = level-1 GEMM1, the ncu target) ----
    half* hph = HB0h; half* hpl = HB0l;
    int n = SEQ, lvl = 0;
    while (n > 1) {
        int Mn = BATCH * (n / 2);
        bool final = (n / 2 == 1);
        half* hoh = (lvl & 1) ? HB0h : HB1h;
        half* hol = (lvl & 1) ? HB0l : HB1l;
        int gy = Mn / BM;
        int total4 = Mn * HDIM / 4;

        // GEMM1 (gates, 1-term): h_hi @ UZRh + [bz|br]
        {
            dim3 grid(2 * HDIM / BN, gy);
            gemm_mma_kernel<1, false><<<grid, 128, GemmCfg<1>::smem>>>(
                hph, nullptr, UZRh, nullptr, BZR, PRE, Mn, 2 * HDIM, 2 * HDIM);
        }
        e1_kernel<<<(total4 + 255) / 256, 256>>>(PRE, hph, hpl, ZB, RHh, total4);
        // GEMM2 (h-tilde, 2-term): rh_hi @ (UHh+UHl) + bh
        {
            dim3 grid(HDIM / BN, gy);
            gemm_mma_kernel<2, false><<<grid, 128, GemmCfg<2>::smem>>>(
                RHh, nullptr, UHh, UHl, BH, PRE, Mn, HDIM, 2 * HDIM);
        }
        if (final)
            e2_kernel<true><<<(total4 + 255) / 256, 256>>>(PRE, ZB, hph, hpl, nullptr, nullptr,
                                                           (float*)d_out, total4);
        else
            e2_kernel<false><<<(total4 + 255) / 256, 256>>>(PRE, ZB, hph, hpl, hoh, hol,
                                                            nullptr, total4);

        hph = hoh; hpl = hol;
        n /= 2;
        lvl++;
    }
    (void)in_sizes; (void)n_in; (void)out_size;
}

// round 14
// speedup vs baseline: 2.0996x; 1.0548x over previous
#include <cuda_runtime.h>
#include <cuda_fp16.h>
#include <math.h>
#include <stdint.h>

// ---------------- problem constants ----------------
#define BATCH   64
#define SEQ     512
#define EDIM    512
#define HDIM    1024
#define VOCAB   32000
#define M0      (BATCH*SEQ)      // 32768 level-0 nodes
#define NSPLIT  4

// ---------------- device scratch (allocation-free rule) ----------------
__device__ half  g_EMBh[(size_t)VOCAB * EDIM];
__device__ half  g_HB0h[(size_t)M0 * HDIM];
__device__ half  g_HB0l[(size_t)M0 * HDIM];
__device__ half  g_HB1h[(size_t)(M0/2) * HDIM];
__device__ half  g_HB1l[(size_t)(M0/2) * HDIM];
__device__ half  g_RHh [(size_t)(M0/2) * 2 * HDIM];
__device__ half  g_W0h [(size_t)(2*HDIM) * EDIM];      // [2048][512]  K-major
__device__ half  g_W0l [(size_t)(2*HDIM) * EDIM];
__device__ half  g_UZRh[(size_t)(2*HDIM) * (2*HDIM)];  // [2048][2048]
__device__ half  g_UHh [(size_t)HDIM * (2*HDIM)];      // [1024][2048]
__device__ half  g_UHl [(size_t)HDIM * (2*HDIM)];
__device__ float g_PRE[(size_t)M0 * 2 * HDIM];
__device__ float g_Z  [(size_t)(M0/2) * HDIM];
__device__ float g_BL0[2*HDIM];
__device__ float g_BZR[2*HDIM];
__device__ float g_BH [HDIM];

// ================= helpers =================
__device__ __forceinline__ uint32_t smem_u32(const void* p) {
    uint32_t a;
    asm("{ .reg .u64 t; cvta.to.shared.u64 t, %1; cvt.u32.u64 %0, t; }" : "=r"(a) : "l"(p));
    return a;
}
__device__ __forceinline__ void split1(float v, half& h, half& l) {
    h = __float2half_rn(v);
    l = __float2half_rn(v - __half2float(h));
}
__device__ __forceinline__ float4 ld4h(const half* p) {
    uint2 u = *(const uint2*)p;
    __half2 a = *(__half2*)&u.x, b = *(__half2*)&u.y;
    float2 fa = __half22float2(a), fb = __half22float2(b);
    return make_float4(fa.x, fa.y, fb.x, fb.y);
}
__device__ __forceinline__ void st4split(half* ph, half* pl, float4 v) {
    half h0, l0, h1, l1, h2, l2, h3, l3;
    split1(v.x, h0, l0); split1(v.y, h1, l1);
    split1(v.z, h2, l2); split1(v.w, h3, l3);
    __half2 H0 = __halves2half2(h0, h1), H1 = __halves2half2(h2, h3);
    __half2 L0 = __halves2half2(l0, l1), L1 = __halves2half2(l2, l3);
    uint2 uh, ul;
    uh.x = *(uint32_t*)&H0; uh.y = *(uint32_t*)&H1;
    ul.x = *(uint32_t*)&L0; ul.y = *(uint32_t*)&L1;
    *(uint2*)ph = uh; *(uint2*)pl = ul;
}
__device__ __forceinline__ void st4hi(half* ph, float4 v) {
    __half2 a = __floats2half2_rn(v.x, v.y);
    __half2 b = __floats2half2_rn(v.z, v.w);
    uint2 u;
    u.x = *(uint32_t*)&a; u.y = *(uint32_t*)&b;
    *(uint2*)ph = u;
}

#define CP16(dst, src) asm volatile("cp.async.cg.shared.global [%0], [%1], 16;" :: "r"(dst), "l"(src))
#define CP_COMMIT()    asm volatile("cp.async.commit_group;" ::: "memory")
#define CP_WAIT(n)     asm volatile("cp.async.wait_group %0;" :: "n"(n) : "memory")

#define LDSM4(r0, r1, r2, r3, addr)                                              \
    asm volatile("ldmatrix.sync.aligned.m8n8.x4.shared.b16 {%0,%1,%2,%3}, [%4];" \
        : "=r"(r0), "=r"(r1), "=r"(r2), "=r"(r3) : "r"(addr))

#define MMA16816(d, a, b0, b1)                                                   \
    asm volatile("mma.sync.aligned.m16n8k16.row.col.f32.f16.f16.f32 "            \
        "{%0,%1,%2,%3}, {%4,%5,%6,%7}, {%8,%9}, {%0,%1,%2,%3};"                  \
        : "+f"((d)[0]), "+f"((d)[1]), "+f"((d)[2]), "+f"((d)[3])                  \
        : "r"((a)[0]), "r"((a)[1]), "r"((a)[2]), "r"((a)[3]), "r"(b0), "r"(b1))

__device__ __forceinline__ float sigmf(float x) { return 1.f / (1.f + expf(-x)); }

// ================= megapack =================
#define NB_EMB   16000
#define NB_W     512
#define NB_U     1024

struct PackArgs {
    const float *emb, *Wz, *Wh, *Uzl, *Url, *Uzr, *Urr, *Uhl, *Uhr;
    const float *bz, *bzl, *bzr, *br, *brl, *brr, *bh, *bhl, *bhr;
};

__device__ void do_transpose_split(const float* __restrict__ src,
                                   half* __restrict__ dh, half* __restrict__ dl,
                                   int R, int C, int dpitch, int blk, int tid,
                                   bool writeLo)
{
    __shared__ float t[32][33];
    int gx = C / 32;
    int c0 = (blk % gx) * 32, r0 = (blk / gx) * 32;
    int x = tid & 31, y = tid >> 5;   // 32 x 8
    #pragma unroll
    for (int i = 0; i < 32; i += 8) {
        t[y + i][x] = src[(size_t)(r0 + y + i) * C + (c0 + x)];
    }
    __syncthreads();
    #pragma unroll
    for (int i = 0; i < 32; i += 8) {
        int c = c0 + y + i, r = r0 + x;
        float v = t[x][y + i];
        half h, l; split1(v, h, l);
        dh[(size_t)c * dpitch + r] = h;
        if (writeLo) dl[(size_t)c * dpitch + r] = l;
    }
}

__global__ void __launch_bounds__(256) megapack_kernel(PackArgs a)
{
    const int tid = threadIdx.x;
    int blk = blockIdx.x;

    if (blk < NB_EMB) {   // emb -> hi plane only
        int q = blk * 256 + tid;
        const int total4 = VOCAB * EDIM / 4;
        if (q < total4) {
            int idx = q * 4;
            float4 v = *(const float4*)(a.emb + idx);
            st4hi(g_EMBh + idx, v);
        }
        return;
    }
    blk -= NB_EMB;
    if (blk < 2 * NB_W) { // W0 transposes (hi+lo)
        if (blk < NB_W) do_transpose_split(a.Wz, g_W0h, g_W0l, 512, 1024, 512, blk, tid, true);
        else            do_transpose_split(a.Wh, g_W0h + (size_t)1024*512, g_W0l + (size_t)1024*512,
                                           512, 1024, 512, blk - NB_W, tid, true);
        return;
    }
    blk -= 2 * NB_W;
    if (blk < 4) {
        int i = blk * 256 + tid;
        float bzs = a.bz[i] + a.bzl[i] + a.bzr[i];
        float brs = a.br[i] + a.brl[i] + a.brr[i];
        float bhs = a.bh[i] + a.bhl[i] + a.bhr[i];
        g_BZR[i] = bzs; g_BZR[1024 + i] = brs;
        g_BH[i]  = bhs;
        g_BL0[i] = bzs; g_BL0[1024 + i] = bhs;
        return;
    }
    blk -= 4;
    {
        int which = blk / NB_U, b = blk % NB_U;
        switch (which) {
            case 0: do_transpose_split(a.Uzl, g_UZRh, nullptr, 1024, 1024, 2048, b, tid, false); break;
            case 1: do_transpose_split(a.Url, g_UZRh + (size_t)1024*2048, nullptr,
                                       1024, 1024, 2048, b, tid, false); break;
            case 2: do_transpose_split(a.Uzr, g_UZRh + 1024, nullptr, 1024, 1024, 2048, b, tid, false); break;
            case 3: do_transpose_split(a.Urr, g_UZRh + (size_t)1024*2048 + 1024, nullptr,
                                       1024, 1024, 2048, b, tid, false); break;
            case 4: do_transpose_split(a.Uhl, g_UHh, g_UHl, 1024, 1024, 2048, b, tid, true); break;
            default: do_transpose_split(a.Uhr, g_UHh + 1024, g_UHl + 1024, 1024, 1024, 2048, b, tid, true); break;
        }
    }
}

// seed PRE with broadcast bias (for split-K accumulation)
__global__ void seed_kernel(float* __restrict__ pre, const float* __restrict__ bias,
                            int total4, int Nmask)
{
    int q = blockIdx.x * blockDim.x + threadIdx.x;
    if (q >= total4) return;
    int idx = q * 4;
    int c = idx & Nmask;
    *(float4*)(pre + idx) = *(const float4*)(bias + c);
}

// ================= mma GEMM, cp.async 3-stage, pipelined =================
// BPL = B planes. A is always hi-only.
// BPL=1: C = Ah@Bh^T (+bias)           4 CTAs/SM.
// BPL=2: C = Ah@(Bh+Bl)^T (+bias)      3 CTAs/SM.
// SPLITK: grid.z=NSPLIT partials, atomicAdd into bias-seeded C.
// BM=64, BN=128, BK=32. 4 warps: 2m x 2n, warp tile 32x64.
#define BM 64
#define BN 128
#define BK 32
#define PAD_B 80
#define NSTAGE 3

template<int BPL>
struct GemmCfg {
    static constexpr int oAH   = 0;
    static constexpr int oBH   = 64 * PAD_B;                       // 5120
    static constexpr int oBL   = 64 * PAD_B + 128 * PAD_B;         // 15360 (BPL2)
    static constexpr int stage = (64 + BPL * 128) * PAD_B;         // 15360 / 25600
    static constexpr int smem  = NSTAGE * stage;                   // 46080 / 76800
    static constexpr int occ   = (BPL == 1) ? 4 : 3;
};

template<int BPL, bool GATHER, bool SPLITK>
__global__ void __launch_bounds__(128, GemmCfg<BPL>::occ)
gemm_mma_kernel(const half* __restrict__ Ah,
                const int* __restrict__ tok,
                const half* __restrict__ Bh, const half* __restrict__ Bl,
                const float* __restrict__ bias,
                float* __restrict__ C, int M, int N, int K)
{
    using Cfg = GemmCfg<BPL>;
    extern __shared__ char smem[];
    const uint32_t sb = smem_u32(smem);
    const int tid  = threadIdx.x;
    const int lane = tid & 31;
    const int wid  = tid >> 5;
    const int warp_m = wid & 1;
    const int warp_n = wid >> 1;
    const int bm = blockIdx.y * BM, bn = blockIdx.x * BN;

    const int NTfull = K / BK;
    const int NT = SPLITK ? NTfull / NSPLIT : NTfull;
    const int gb = SPLITK ? (int)(blockIdx.z * NT) * 64 : 0;   // global k byte offset

    // ---- compact cp.async addressing ----
    const int r0  = tid >> 2;
    const int seg = (tid & 3) * 16;
    const uint32_t dstA0 = (uint32_t)(r0 * PAD_B + seg);
    const int KB = K * 64;   // bytes per 32 K-major rows (32 * K * 2)
    size_t arow0, arow1;
    if (GATHER) { arow0 = (size_t)__ldg(&tok[bm + r0]); arow1 = (size_t)__ldg(&tok[bm + r0 + 32]); }
    else        { arow0 = (size_t)(bm + r0);            arow1 = (size_t)(bm + r0 + 32); }
    const char* pA0 = (const char*)(Ah + arow0 * K) + seg + gb;
    const char* pA1 = (const char*)(Ah + arow1 * K) + seg + gb;
    const char* pB  = (const char*)(Bh + (size_t)(bn + r0) * K) + seg + gb;
    const char* pBl = (BPL == 2) ? (const char*)(Bl + (size_t)(bn + r0) * K) + seg + gb : nullptr;

    auto issue = [&](int kt) {
        if (kt < NT) {
            const uint32_t d = sb + (kt % NSTAGE) * Cfg::stage + dstA0;
            const int g = kt * 64;
            CP16(d + Cfg::oAH,        pA0 + g);
            CP16(d + Cfg::oAH + 2560, pA1 + g);
            #pragma unroll
            for (int j = 0; j < 4; j++)
                CP16(d + Cfg::oBH + j * 2560, pB + (size_t)j * KB + g);
            if (BPL == 2) {
                #pragma unroll
                for (int j = 0; j < 4; j++)
                    CP16(d + Cfg::oBL + j * 2560, pBl + (size_t)j * KB + g);
            }
        }
        CP_COMMIT();
    };

    const uint32_t a_lane_off = (uint32_t)((warp_m * 32 + (lane & 15)) * PAD_B + ((lane >> 4) * 8) * 2);
    const uint32_t b_lane_off = (uint32_t)((warp_n * 64 + ((lane >> 4) << 3) + (lane & 7)) * PAD_B
                                           + (((lane >> 3) & 1) * 8) * 2);

    float acc[2][8][4];
    #pragma unroll
    for (int mt = 0; mt < 2; mt++)
        #pragma unroll
        for (int t = 0; t < 8; t++)
            #pragma unroll
            for (int j = 0; j < 4; j++) acc[mt][t][j] = 0.f;

    issue(0);
    issue(1);

#define LDSM_A(arr, ks)                                                           \
    _Pragma("unroll")                                                             \
    for (int mt = 0; mt < 2; mt++) {                                              \
        uint32_t ad = sbase + a_lane_off + mt * (16 * PAD_B) + (ks) * 32;         \
        LDSM4(arr[mt][0], arr[mt][1], arr[mt][2], arr[mt][3], ad + Cfg::oAH);     \
    }
#define LDSM_B(arr, ks, OFS)                                                      \
    _Pragma("unroll")                                                             \
    for (int ng = 0; ng < 4; ng++) {                                              \
        uint32_t bd = sbase + b_lane_off + ng * (16 * PAD_B) + (ks) * 32;         \
        LDSM4(arr[ng][0], arr[ng][1], arr[ng][2], arr[ng][3], bd + OFS);          \
    }
#define DO_MMA1(aF, bF)                                                           \
    _Pragma("unroll")                                                             \
    for (int mt = 0; mt < 2; mt++)                                                \
        _Pragma("unroll")                                                         \
        for (int ng = 0; ng < 4; ng++)                                            \
            _Pragma("unroll")                                                     \
            for (int p = 0; p < 2; p++)                                           \
                MMA16816(acc[mt][ng * 2 + p], aF[mt], bF[ng][2 * p], bF[ng][2 * p + 1]);
#define DO_MMA2(aF, bF, cF)                                                       \
    _Pragma("unroll")                                                             \
    for (int mt = 0; mt < 2; mt++)                                                \
        _Pragma("unroll")                                                         \
        for (int ng = 0; ng < 4; ng++)                                            \
            _Pragma("unroll")                                                     \
            for (int p = 0; p < 2; p++) {                                         \
                MMA16816(acc[mt][ng * 2 + p], aF[mt], bF[ng][2 * p], bF[ng][2 * p + 1]); \
                MMA16816(acc[mt][ng * 2 + p], aF[mt], cF[ng][2 * p], cF[ng][2 * p + 1]); \
            }

    for (int kt = 0; kt < NT; kt++) {
        CP_WAIT(1);
        __syncthreads();
        const uint32_t sbase = sb + (kt % NSTAGE) * Cfg::stage;

        if (BPL == 1) {
            uint32_t a0[2][4], b0[4][4];
            LDSM_A(a0, 0); LDSM_B(b0, 0, Cfg::oBH);
            issue(kt + 2);
            DO_MMA1(a0, b0);
            uint32_t a1[2][4], b1[4][4];
            LDSM_A(a1, 1); LDSM_B(b1, 1, Cfg::oBH);
            DO_MMA1(a1, b1);
        } else {
            uint32_t a0[2][4], b0[4][4], c0[4][4];
            LDSM_A(a0, 0); LDSM_B(b0, 0, Cfg::oBH); LDSM_B(c0, 0, Cfg::oBL);
            issue(kt + 2);
            uint32_t a1[2][4], b1[4][4], c1[4][4];
            LDSM_A(a1, 1); LDSM_B(b1, 1, Cfg::oBH); LDSM_B(c1, 1, Cfg::oBL);
            DO_MMA2(a0, b0, c0);
            DO_MMA2(a1, b1, c1);
        }
    }

    // ---- epilogue ----
    const int r0e = bm + warp_m * 32 + (lane >> 2);
    const int c0e = bn + warp_n * 64 + (lane & 3) * 2;
    #pragma unroll
    for (int mt = 0; mt < 2; mt++) {
        const int row = r0e + mt * 16;
        #pragma unroll
        for (int t = 0; t < 8; t++) {
            const int col = c0e + t * 8;
            if (SPLITK) {
                atomicAdd(C + (size_t)row * N + col,           acc[mt][t][0]);
                atomicAdd(C + (size_t)row * N + col + 1,       acc[mt][t][1]);
                atomicAdd(C + (size_t)(row + 8) * N + col,     acc[mt][t][2]);
                atomicAdd(C + (size_t)(row + 8) * N + col + 1, acc[mt][t][3]);
            } else {
                const float b0 = bias[col], b1 = bias[col + 1];
                float2 v0 = make_float2(acc[mt][t][0] + b0, acc[mt][t][1] + b1);
                *(float2*)(C + (size_t)row * N + col) = v0;
                float2 v1 = make_float2(acc[mt][t][2] + b0, acc[mt][t][3] + b1);
                *(float2*)(C + (size_t)(row + 8) * N + col) = v1;
            }
        }
    }
}

// ================= elementwise epilogues =================
__global__ void e0_kernel(const float* __restrict__ pre,
                          half* __restrict__ hh, half* __restrict__ hl, int total4)
{
    int q = blockIdx.x * blockDim.x + threadIdx.x;
    if (q >= total4) return;
    int idx = q * 4;
    int m = idx >> 10, j = idx & 1023;
    size_t o = (size_t)m * 2048 + j;
    float4 zp = *(const float4*)(pre + o);
    float4 hp = *(const float4*)(pre + o + 1024);
    float4 r;
    r.x = (1.f - sigmf(zp.x)) * tanhf(hp.x);
    r.y = (1.f - sigmf(zp.y)) * tanhf(hp.y);
    r.z = (1.f - sigmf(zp.z)) * tanhf(hp.z);
    r.w = (1.f - sigmf(zp.w)) * tanhf(hp.w);
    st4split(hh + idx, hl + idx, r);
}

__global__ void e1_kernel(const float* __restrict__ pre,
                          const half* __restrict__ hph, const half* __restrict__ hpl,
                          float* __restrict__ zb,
                          half* __restrict__ rhh, int total4)
{
    int q = blockIdx.x * blockDim.x + threadIdx.x;
    if (q >= total4) return;
    int idx = q * 4;
    int m = idx >> 10, j = idx & 1023;
    size_t o = (size_t)m * 2048 + j;
    float4 zp = *(const float4*)(pre + o);
    float4 rp = *(const float4*)(pre + o + 1024);
    float4 Hh = ld4h(hph + o),        Lh = ld4h(hpl + o);
    float4 Hr = ld4h(hph + o + 1024), Lr = ld4h(hpl + o + 1024);
    float hlx = Hh.x + Lh.x, hly = Hh.y + Lh.y, hlz = Hh.z + Lh.z, hlw = Hh.w + Lh.w;
    float hrx = Hr.x + Lr.x, hry = Hr.y + Lr.y, hrz = Hr.z + Lr.z, hrw = Hr.w + Lr.w;
    float4 z;
    z.x = sigmf(zp.x); z.y = sigmf(zp.y); z.z = sigmf(zp.z); z.w = sigmf(zp.w);
    float rx = sigmf(rp.x), ry = sigmf(rp.y), rz = sigmf(rp.z), rw = sigmf(rp.w);
    *(float4*)(zb + idx) = z;
    st4hi(rhh + o,        make_float4(rx * hlx, ry * hly, rz * hlz, rw * hlw));
    st4hi(rhh + o + 1024, make_float4(rx * hrx, ry * hry, rz * hrz, rw * hrw));
}

template<bool FINAL>
__global__ void e2_kernel(const float* __restrict__ pre2, const float* __restrict__ zb,
                          const half* __restrict__ hph, const half* __restrict__ hpl,
                          half* __restrict__ hoh, half* __restrict__ hol,
                          float* __restrict__ outf, int total4)
{
    int q = blockIdx.x * blockDim.x + threadIdx.x;
    if (q >= total4) return;
    int idx = q * 4;
    int m = idx >> 10, j = idx & 1023;
    size_t o = (size_t)m * 2048 + j;
    float4 z  = *(const float4*)(zb + idx);
    float4 p  = *(const float4*)(pre2 + idx);
    float4 Hh = ld4h(hph + o),        Lh = ld4h(hpl + o);
    float4 Hr = ld4h(hph + o + 1024), Lr = ld4h(hpl + o + 1024);
    float4 r;
    r.x = z.x * ((Hh.x + Lh.x) + (Hr.x + Lr.x)) + (1.f - z.x) * tanhf(p.x);
    r.y = z.y * ((Hh.y + Lh.y) + (Hr.y + Lr.y)) + (1.f - z.y) * tanhf(p.y);
    r.z = z.z * ((Hh.z + Lh.z) + (Hr.z + Lr.z)) + (1.f - z.z) * tanhf(p.z);
    r.w = z.w * ((Hh.w + Lh.w) + (Hr.w + Lr.w)) + (1.f - z.w) * tanhf(p.w);
    if (FINAL) *(float4*)(outf + idx) = r;
    else       st4split(hoh + idx, hol + idx, r);
}

// ================= launch =================
extern "C" void kernel_launch(void* const* d_in, const int* in_sizes, int n_in,
                              void* d_out, int out_size)
{
    const int*   tokens = (const int*)  d_in[0];
    const float* emb    = (const float*)d_in[1];

    PackArgs pa;
    pa.emb = emb;
    pa.Wz  = (const float*)d_in[2];
    pa.bz  = (const float*)d_in[3];
    pa.Uzl = (const float*)d_in[4];
    pa.bzl = (const float*)d_in[5];
    pa.Uzr = (const float*)d_in[6];
    pa.bzr = (const float*)d_in[7];
    pa.br  = (const float*)d_in[9];
    pa.Url = (const float*)d_in[10];
    pa.brl = (const float*)d_in[11];
    pa.Urr = (const float*)d_in[12];
    pa.brr = (const float*)d_in[13];
    pa.Wh  = (const float*)d_in[14];
    pa.bh  = (const float*)d_in[15];
    pa.Uhl = (const float*)d_in[16];
    pa.bhl = (const float*)d_in[17];
    pa.Uhr = (const float*)d_in[18];
    pa.bhr = (const float*)d_in[19];

    half *EMBh, *HB0h, *HB0l, *HB1h, *HB1l, *RHh;
    half *W0h, *W0l, *UZRh, *UHh, *UHl;
    float *PRE, *ZB, *BL0, *BZR, *BH;
    cudaGetSymbolAddress((void**)&EMBh, g_EMBh);
    cudaGetSymbolAddress((void**)&HB0h, g_HB0h);
    cudaGetSymbolAddress((void**)&HB0l, g_HB0l);
    cudaGetSymbolAddress((void**)&HB1h, g_HB1h);
    cudaGetSymbolAddress((void**)&HB1l, g_HB1l);
    cudaGetSymbolAddress((void**)&RHh,  g_RHh);
    cudaGetSymbolAddress((void**)&W0h,  g_W0h);
    cudaGetSymbolAddress((void**)&W0l,  g_W0l);
    cudaGetSymbolAddress((void**)&UZRh, g_UZRh);
    cudaGetSymbolAddress((void**)&UHh,  g_UHh);
    cudaGetSymbolAddress((void**)&UHl,  g_UHl);
    cudaGetSymbolAddress((void**)&PRE,  g_PRE);
    cudaGetSymbolAddress((void**)&ZB,   g_Z);
    cudaGetSymbolAddress((void**)&BL0,  g_BL0);
    cudaGetSymbolAddress((void**)&BZR,  g_BZR);
    cudaGetSymbolAddress((void**)&BH,   g_BH);

    cudaFuncSetAttribute(gemm_mma_kernel<2, true,  false>,
                         cudaFuncAttributeMaxDynamicSharedMemorySize, GemmCfg<2>::smem);
    cudaFuncSetAttribute(gemm_mma_kernel<2, false, false>,
                         cudaFuncAttributeMaxDynamicSharedMemorySize, GemmCfg<2>::smem);
    cudaFuncSetAttribute(gemm_mma_kernel<2, false, true>,
                         cudaFuncAttributeMaxDynamicSharedMemorySize, GemmCfg<2>::smem);
    cudaFuncSetAttribute(gemm_mma_kernel<1, false, false>,
                         cudaFuncAttributeMaxDynamicSharedMemorySize, GemmCfg<1>::smem);
    cudaFuncSetAttribute(gemm_mma_kernel<1, false, true>,
                         cudaFuncAttributeMaxDynamicSharedMemorySize, GemmCfg<1>::smem);

    // ---- launch 0: megapack ----
    {
        int nblocks = NB_EMB + 2 * NB_W + 4 + 6 * NB_U;
        megapack_kernel<<<nblocks, 256>>>(pa);
    }

    // ---- launch 1: level-0 GEMM ; launch 2: e0 ----
    {
        dim3 grid(2 * HDIM / BN, M0 / BM);
        gemm_mma_kernel<2, true, false><<<grid, 128, GemmCfg<2>::smem>>>(
            EMBh, tokens, W0h, W0l, BL0, PRE, M0, 2 * HDIM, EDIM);
        int total4 = M0 * HDIM / 4;
        e0_kernel<<<(total4 + 255) / 256, 256>>>(PRE, HB0h, HB0l, total4);
    }

    // ---- tree levels (launch 3 = level-1 GEMM1, the ncu target) ----
    half* hph = HB0h; half* hpl = HB0l;
    int n = SEQ, lvl = 0;
    while (n > 1) {
        int Mn = BATCH * (n / 2);
        bool final = (n / 2 == 1);
        bool sk = (Mn <= 512);
        half* hoh = (lvl & 1) ? HB0h : HB1h;
        half* hol = (lvl & 1) ? HB0l : HB1l;
        int gy = Mn / BM;
        int total4 = Mn * HDIM / 4;

        // GEMM1 (gates, 1-term): h_hi @ UZRh + [bz|br]
        if (sk) {
            int t4 = Mn * 2 * HDIM / 4;
            seed_kernel<<<(t4 + 255) / 256, 256>>>(PRE, BZR, t4, 2 * HDIM - 1);
            dim3 grid(2 * HDIM / BN, gy, NSPLIT);
            gemm_mma_kernel<1, false, true><<<grid, 128, GemmCfg<1>::smem>>>(
                hph, nullptr, UZRh, nullptr, BZR, PRE, Mn, 2 * HDIM, 2 * HDIM);
        } else {
            dim3 grid(2 * HDIM / BN, gy);
            gemm_mma_kernel<1, false, false><<<grid, 128, GemmCfg<1>::smem>>>(
                hph, nullptr, UZRh, nullptr, BZR, PRE, Mn, 2 * HDIM, 2 * HDIM);
        }
        e1_kernel<<<(total4 + 255) / 256, 256>>>(PRE, hph, hpl, ZB, RHh, total4);
        // GEMM2 (h-tilde, 2-term): rh_hi @ (UHh+UHl) + bh
        if (sk) {
            int t4 = Mn * HDIM / 4;
            seed_kernel<<<(t4 + 255) / 256, 256>>>(PRE, BH, t4, HDIM - 1);
            dim3 grid(HDIM / BN, gy, NSPLIT);
            gemm_mma_kernel<2, false, true><<<grid, 128, GemmCfg<2>::smem>>>(
                RHh, nullptr, UHh, UHl, BH, PRE, Mn, HDIM, 2 * HDIM);
        } else {
            dim3 grid(HDIM / BN, gy);
            gemm_mma_kernel<2, false, false><<<grid, 128, GemmCfg<2>::smem>>>(
                RHh, nullptr, UHh, UHl, BH, PRE, Mn, HDIM, 2 * HDIM);
        }
        if (final)
            e2_kernel<true><<<(total4 + 255) / 256, 256>>>(PRE, ZB, hph, hpl, nullptr, nullptr,
                                                           (float*)d_out, total4);
        else
            e2_kernel<false><<<(total4 + 255) / 256, 256>>>(PRE, ZB, hph, hpl, hoh, hol,
                                                            nullptr, total4);

        hph = hoh; hpl = hol;
        n /= 2;
        lvl++;
    }
    (void)in_sizes; (void)n_in; (void)out_size;
}

// round 15
// speedup vs baseline: 2.2478x; 1.0706x over previous
#include <cuda_runtime.h>
#include <cuda_fp16.h>
#include <math.h>
#include <stdint.h>

// ---------------- problem constants ----------------
#define BATCH   64
#define SEQ     512
#define EDIM    512
#define HDIM    1024
#define VOCAB   32000
#define M0      (BATCH*SEQ)      // 32768 level-0 nodes
#define NSPLIT  4

// ---------------- device scratch (allocation-free rule) ----------------
__device__ half  g_EMBh[(size_t)VOCAB * EDIM];
__device__ half  g_HB0h[(size_t)M0 * HDIM];
__device__ half  g_HB0l[(size_t)M0 * HDIM];
__device__ half  g_HB1h[(size_t)(M0/2) * HDIM];
__device__ half  g_HB1l[(size_t)(M0/2) * HDIM];
__device__ half  g_RHh [(size_t)(M0/2) * 2 * HDIM];
__device__ half  g_W0h [(size_t)(2*HDIM) * EDIM];      // [2048][512]  K-major
__device__ half  g_W0l [(size_t)(2*HDIM) * EDIM];
__device__ half  g_UZRh[(size_t)(2*HDIM) * (2*HDIM)];  // [2048][2048]
__device__ half  g_UHh [(size_t)HDIM * (2*HDIM)];      // [1024][2048]
__device__ half  g_UHl [(size_t)HDIM * (2*HDIM)];
__device__ float g_PRE[(size_t)M0 * 2 * HDIM];
__device__ float g_Z  [(size_t)(M0/2) * HDIM];
__device__ float g_BL0[2*HDIM];
__device__ float g_BZR[2*HDIM];
__device__ float g_BH [HDIM];

// ================= helpers =================
__device__ __forceinline__ uint32_t smem_u32(const void* p) {
    uint32_t a;
    asm("{ .reg .u64 t; cvta.to.shared.u64 t, %1; cvt.u32.u64 %0, t; }" : "=r"(a) : "l"(p));
    return a;
}
__device__ __forceinline__ void split1(float v, half& h, half& l) {
    h = __float2half_rn(v);
    l = __float2half_rn(v - __half2float(h));
}
__device__ __forceinline__ float4 ld4h(const half* p) {
    uint2 u = *(const uint2*)p;
    __half2 a = *(__half2*)&u.x, b = *(__half2*)&u.y;
    float2 fa = __half22float2(a), fb = __half22float2(b);
    return make_float4(fa.x, fa.y, fb.x, fb.y);
}
__device__ __forceinline__ void st4split(half* ph, half* pl, float4 v) {
    half h0, l0, h1, l1, h2, l2, h3, l3;
    split1(v.x, h0, l0); split1(v.y, h1, l1);
    split1(v.z, h2, l2); split1(v.w, h3, l3);
    __half2 H0 = __halves2half2(h0, h1), H1 = __halves2half2(h2, h3);
    __half2 L0 = __halves2half2(l0, l1), L1 = __halves2half2(l2, l3);
    uint2 uh, ul;
    uh.x = *(uint32_t*)&H0; uh.y = *(uint32_t*)&H1;
    ul.x = *(uint32_t*)&L0; ul.y = *(uint32_t*)&L1;
    *(uint2*)ph = uh; *(uint2*)pl = ul;
}
__device__ __forceinline__ void st4hi(half* ph, float4 v) {
    __half2 a = __floats2half2_rn(v.x, v.y);
    __half2 b = __floats2half2_rn(v.z, v.w);
    uint2 u;
    u.x = *(uint32_t*)&a; u.y = *(uint32_t*)&b;
    *(uint2*)ph = u;
}

#define CP16(dst, src) asm volatile("cp.async.cg.shared.global [%0], [%1], 16;" :: "r"(dst), "l"(src))
#define CP_COMMIT()    asm volatile("cp.async.commit_group;" ::: "memory")
#define CP_WAIT(n)     asm volatile("cp.async.wait_group %0;" :: "n"(n) : "memory")

#define LDSM4(r0, r1, r2, r3, addr)                                              \
    asm volatile("ldmatrix.sync.aligned.m8n8.x4.shared.b16 {%0,%1,%2,%3}, [%4];" \
        : "=r"(r0), "=r"(r1), "=r"(r2), "=r"(r3) : "r"(addr))

#define MMA16816(d, a, b0, b1)                                                   \
    asm volatile("mma.sync.aligned.m16n8k16.row.col.f32.f16.f16.f32 "            \
        "{%0,%1,%2,%3}, {%4,%5,%6,%7}, {%8,%9}, {%0,%1,%2,%3};"                  \
        : "+f"((d)[0]), "+f"((d)[1]), "+f"((d)[2]), "+f"((d)[3])                  \
        : "r"((a)[0]), "r"((a)[1]), "r"((a)[2]), "r"((a)[3]), "r"(b0), "r"(b1))

__device__ __forceinline__ float sigmf(float x) { return 1.f / (1.f + expf(-x)); }

// ================= megapack =================
#define NB_EMB   16000
#define NB_W     512
#define NB_U     1024

struct PackArgs {
    const float *emb, *Wz, *Wh, *Uzl, *Url, *Uzr, *Urr, *Uhl, *Uhr;
    const float *bz, *bzl, *bzr, *br, *brl, *brr, *bh, *bhl, *bhr;
};

__device__ void do_transpose_split(const float* __restrict__ src,
                                   half* __restrict__ dh, half* __restrict__ dl,
                                   int R, int C, int dpitch, int blk, int tid,
                                   bool writeLo)
{
    __shared__ float t[32][33];
    int gx = C / 32;
    int c0 = (blk % gx) * 32, r0 = (blk / gx) * 32;
    int x = tid & 31, y = tid >> 5;   // 32 x 8
    #pragma unroll
    for (int i = 0; i < 32; i += 8) {
        t[y + i][x] = src[(size_t)(r0 + y + i) * C + (c0 + x)];
    }
    __syncthreads();
    #pragma unroll
    for (int i = 0; i < 32; i += 8) {
        int c = c0 + y + i, r = r0 + x;
        float v = t[x][y + i];
        half h, l; split1(v, h, l);
        dh[(size_t)c * dpitch + r] = h;
        if (writeLo) dl[(size_t)c * dpitch + r] = l;
    }
}

__global__ void __launch_bounds__(256) megapack_kernel(PackArgs a)
{
    const int tid = threadIdx.x;
    int blk = blockIdx.x;

    if (blk < NB_EMB) {   // emb -> hi plane only
        int q = blk * 256 + tid;
        const int total4 = VOCAB * EDIM / 4;
        if (q < total4) {
            int idx = q * 4;
            float4 v = *(const float4*)(a.emb + idx);
            st4hi(g_EMBh + idx, v);
        }
        return;
    }
    blk -= NB_EMB;
    if (blk < 2 * NB_W) { // W0 transposes (hi+lo)
        if (blk < NB_W) do_transpose_split(a.Wz, g_W0h, g_W0l, 512, 1024, 512, blk, tid, true);
        else            do_transpose_split(a.Wh, g_W0h + (size_t)1024*512, g_W0l + (size_t)1024*512,
                                           512, 1024, 512, blk - NB_W, tid, true);
        return;
    }
    blk -= 2 * NB_W;
    if (blk < 4) {
        int i = blk * 256 + tid;
        float bzs = a.bz[i] + a.bzl[i] + a.bzr[i];
        float brs = a.br[i] + a.brl[i] + a.brr[i];
        float bhs = a.bh[i] + a.bhl[i] + a.bhr[i];
        g_BZR[i] = bzs; g_BZR[1024 + i] = brs;
        g_BH[i]  = bhs;
        g_BL0[i] = bzs; g_BL0[1024 + i] = bhs;
        return;
    }
    blk -= 4;
    {
        int which = blk / NB_U, b = blk % NB_U;
        switch (which) {
            case 0: do_transpose_split(a.Uzl, g_UZRh, nullptr, 1024, 1024, 2048, b, tid, false); break;
            case 1: do_transpose_split(a.Url, g_UZRh + (size_t)1024*2048, nullptr,
                                       1024, 1024, 2048, b, tid, false); break;
            case 2: do_transpose_split(a.Uzr, g_UZRh + 1024, nullptr, 1024, 1024, 2048, b, tid, false); break;
            case 3: do_transpose_split(a.Urr, g_UZRh + (size_t)1024*2048 + 1024, nullptr,
                                       1024, 1024, 2048, b, tid, false); break;
            case 4: do_transpose_split(a.Uhl, g_UHh, g_UHl, 1024, 1024, 2048, b, tid, true); break;
            default: do_transpose_split(a.Uhr, g_UHh + 1024, g_UHl + 1024, 1024, 1024, 2048, b, tid, true); break;
        }
    }
}

// seed PRE with broadcast bias (for split-K accumulation)
__global__ void seed_kernel(float* __restrict__ pre, const float* __restrict__ bias,
                            int total4, int Nmask)
{
    int q = blockIdx.x * blockDim.x + threadIdx.x;
    if (q >= total4) return;
    int idx = q * 4;
    int c = idx & Nmask;
    *(float4*)(pre + idx) = *(const float4*)(bias + c);
}

// ================= mma GEMM, cp.async 3-stage =================
// BPL = B planes (A hi-only). BMT = CTA M tile (64 or 128). BN=128 fixed.
// Warp tile always 32x64: BMT/32 m-warps x 2 n-warps, TC = BMT*2 threads.
#define BN 128
#define BK 32
#define PAD_B 80
#define NSTAGE 3

template<int BPL, int BMT>
struct GemmCfg {
    static constexpr int TC    = BMT * 2;             // threads (128 or 256)
    static constexpr int WM    = BMT / 32;            // m-warps
    static constexpr int RT    = BMT + BPL * 128;     // rows per stage
    static constexpr int nseg  = RT * 4 / TC;         // 16B segs per thread
    static constexpr int oBH   = BMT * PAD_B;
    static constexpr int stage = RT * PAD_B;
    static constexpr int smem  = NSTAGE * stage;
    static constexpr int occ   = (BMT == 128) ? 2 : ((BPL == 1) ? 4 : 3);
};

template<int BPL, int BMT, bool GATHER, bool SPLITK>
__global__ void __launch_bounds__(GemmCfg<BPL, BMT>::TC, GemmCfg<BPL, BMT>::occ)
gemm_mma_kernel(const half* __restrict__ Ah,
                const int* __restrict__ tok,
                const half* __restrict__ Bh, const half* __restrict__ Bl,
                const float* __restrict__ bias,
                float* __restrict__ C, int M, int N, int K)
{
    using Cfg = GemmCfg<BPL, BMT>;
    extern __shared__ char smem[];
    const uint32_t sb = smem_u32(smem);
    const int tid  = threadIdx.x;
    const int lane = tid & 31;
    const int wid  = tid >> 5;
    const int warp_m = wid % Cfg::WM;
    const int warp_n = wid / Cfg::WM;
    const int bm = blockIdx.y * BMT, bn = blockIdx.x * BN;

    const int NTfull = K / BK;
    const int NT = SPLITK ? NTfull / NSPLIT : NTfull;
    const int gb = SPLITK ? (int)(blockIdx.z * NT) * 64 : 0;

    // ---- cp.async mapping: nseg x 16B per thread per stage, unified dst ----
    const char* srcp[Cfg::nseg];
    uint32_t    dsto[Cfg::nseg];
    #pragma unroll
    for (int i = 0; i < Cfg::nseg; i++) {
        int s   = tid + Cfg::TC * i;
        int row = s >> 2;
        int sg  = (s & 3) * 16;
        dsto[i] = (uint32_t)(row * PAD_B + sg);
        if (row < BMT) {
            int gr = bm + row;
            size_t ar = GATHER ? (size_t)__ldg(&tok[gr]) : (size_t)gr;
            srcp[i] = (const char*)(Ah + ar * K) + sg + gb;
        } else if (row < BMT + 128) {
            srcp[i] = (const char*)(Bh + (size_t)(bn + row - BMT) * K) + sg + gb;
        } else {
            srcp[i] = (const char*)(Bl + (size_t)(bn + row - BMT - 128) * K) + sg + gb;
        }
    }

    auto issue = [&](int kt) {
        if (kt < NT) {
            const uint32_t d = sb + (kt % NSTAGE) * Cfg::stage;
            const int g = kt * 64;
            #pragma unroll
            for (int i = 0; i < Cfg::nseg; i++) CP16(d + dsto[i], srcp[i] + g);
        }
        CP_COMMIT();
    };

    const uint32_t a_lane_off = (uint32_t)((warp_m * 32 + (lane & 15)) * PAD_B + ((lane >> 4) * 8) * 2);
    const uint32_t b_lane_off = (uint32_t)((warp_n * 64 + ((lane >> 4) << 3) + (lane & 7)) * PAD_B
                                           + (((lane >> 3) & 1) * 8) * 2);

    float acc[2][8][4];
    #pragma unroll
    for (int mt = 0; mt < 2; mt++)
        #pragma unroll
        for (int t = 0; t < 8; t++)
            #pragma unroll
            for (int j = 0; j < 4; j++) acc[mt][t][j] = 0.f;

    issue(0);
    issue(1);

#define LDSM_A(arr, ks)                                                           \
    _Pragma("unroll")                                                             \
    for (int mt = 0; mt < 2; mt++) {                                              \
        uint32_t ad = sbase + a_lane_off + mt * (16 * PAD_B) + (ks) * 32;         \
        LDSM4(arr[mt][0], arr[mt][1], arr[mt][2], arr[mt][3], ad);                \
    }
#define LDSM_B(arr, ks, OFS)                                                      \
    _Pragma("unroll")                                                             \
    for (int ng = 0; ng < 4; ng++) {                                              \
        uint32_t bd = sbase + b_lane_off + ng * (16 * PAD_B) + (ks) * 32;         \
        LDSM4(arr[ng][0], arr[ng][1], arr[ng][2], arr[ng][3], bd + OFS);          \
    }
#define DO_MMA1(aF, bF)                                                           \
    _Pragma("unroll")                                                             \
    for (int mt = 0; mt < 2; mt++)                                                \
        _Pragma("unroll")                                                         \
        for (int ng = 0; ng < 4; ng++)                                            \
            _Pragma("unroll")                                                     \
            for (int p = 0; p < 2; p++)                                           \
                MMA16816(acc[mt][ng * 2 + p], aF[mt], bF[ng][2 * p], bF[ng][2 * p + 1]);
#define DO_MMA2(aF, bF, cF)                                                       \
    _Pragma("unroll")                                                             \
    for (int mt = 0; mt < 2; mt++)                                                \
        _Pragma("unroll")                                                         \
        for (int ng = 0; ng < 4; ng++)                                            \
            _Pragma("unroll")                                                     \
            for (int p = 0; p < 2; p++) {                                         \
                MMA16816(acc[mt][ng * 2 + p], aF[mt], bF[ng][2 * p], bF[ng][2 * p + 1]); \
                MMA16816(acc[mt][ng * 2 + p], aF[mt], cF[ng][2 * p], cF[ng][2 * p + 1]); \
            }

    for (int kt = 0; kt < NT; kt++) {
        CP_WAIT(1);
        __syncthreads();
        const uint32_t sbase = sb + (kt % NSTAGE) * Cfg::stage;

        if (BPL == 1) {
            uint32_t a0[2][4], b0[4][4];
            LDSM_A(a0, 0); LDSM_B(b0, 0, Cfg::oBH);
            issue(kt + 2);
            DO_MMA1(a0, b0);
            uint32_t a1[2][4], b1[4][4];
            LDSM_A(a1, 1); LDSM_B(b1, 1, Cfg::oBH);
            DO_MMA1(a1, b1);
        } else {
            uint32_t a0[2][4], b0[4][4], c0[4][4];
            LDSM_A(a0, 0); LDSM_B(b0, 0, Cfg::oBH); LDSM_B(c0, 0, Cfg::oBH + 128 * PAD_B);
            issue(kt + 2);
            uint32_t a1[2][4], b1[4][4], c1[4][4];
            LDSM_A(a1, 1); LDSM_B(b1, 1, Cfg::oBH); LDSM_B(c1, 1, Cfg::oBH + 128 * PAD_B);
            DO_MMA2(a0, b0, c0);
            DO_MMA2(a1, b1, c1);
        }
    }

    // ---- epilogue ----
    const int r0e = bm + warp_m * 32 + (lane >> 2);
    const int c0e = bn + warp_n * 64 + (lane & 3) * 2;
    #pragma unroll
    for (int mt = 0; mt < 2; mt++) {
        const int row = r0e + mt * 16;
        #pragma unroll
        for (int t = 0; t < 8; t++) {
            const int col = c0e + t * 8;
            if (SPLITK) {
                atomicAdd(C + (size_t)row * N + col,           acc[mt][t][0]);
                atomicAdd(C + (size_t)row * N + col + 1,       acc[mt][t][1]);
                atomicAdd(C + (size_t)(row + 8) * N + col,     acc[mt][t][2]);
                atomicAdd(C + (size_t)(row + 8) * N + col + 1, acc[mt][t][3]);
            } else {
                const float b0 = bias[col], b1 = bias[col + 1];
                float2 v0 = make_float2(acc[mt][t][0] + b0, acc[mt][t][1] + b1);
                *(float2*)(C + (size_t)row * N + col) = v0;
                float2 v1 = make_float2(acc[mt][t][2] + b0, acc[mt][t][3] + b1);
                *(float2*)(C + (size_t)(row + 8) * N + col) = v1;
            }
        }
    }
}

// ================= elementwise epilogues =================
__global__ void e0_kernel(const float* __restrict__ pre,
                          half* __restrict__ hh, half* __restrict__ hl, int total4)
{
    int q = blockIdx.x * blockDim.x + threadIdx.x;
    if (q >= total4) return;
    int idx = q * 4;
    int m = idx >> 10, j = idx & 1023;
    size_t o = (size_t)m * 2048 + j;
    float4 zp = *(const float4*)(pre + o);
    float4 hp = *(const float4*)(pre + o + 1024);
    float4 r;
    r.x = (1.f - sigmf(zp.x)) * tanhf(hp.x);
    r.y = (1.f - sigmf(zp.y)) * tanhf(hp.y);
    r.z = (1.f - sigmf(zp.z)) * tanhf(hp.z);
    r.w = (1.f - sigmf(zp.w)) * tanhf(hp.w);
    st4split(hh + idx, hl + idx, r);
}

__global__ void e1_kernel(const float* __restrict__ pre,
                          const half* __restrict__ hph, const half* __restrict__ hpl,
                          float* __restrict__ zb,
                          half* __restrict__ rhh, int total4)
{
    int q = blockIdx.x * blockDim.x + threadIdx.x;
    if (q >= total4) return;
    int idx = q * 4;
    int m = idx >> 10, j = idx & 1023;
    size_t o = (size_t)m * 2048 + j;
    float4 zp = *(const float4*)(pre + o);
    float4 rp = *(const float4*)(pre + o + 1024);
    float4 Hh = ld4h(hph + o),        Lh = ld4h(hpl + o);
    float4 Hr = ld4h(hph + o + 1024), Lr = ld4h(hpl + o + 1024);
    float hlx = Hh.x + Lh.x, hly = Hh.y + Lh.y, hlz = Hh.z + Lh.z, hlw = Hh.w + Lh.w;
    float hrx = Hr.x + Lr.x, hry = Hr.y + Lr.y, hrz = Hr.z + Lr.z, hrw = Hr.w + Lr.w;
    float4 z;
    z.x = sigmf(zp.x); z.y = sigmf(zp.y); z.z = sigmf(zp.z); z.w = sigmf(zp.w);
    float rx = sigmf(rp.x), ry = sigmf(rp.y), rz = sigmf(rp.z), rw = sigmf(rp.w);
    *(float4*)(zb + idx) = z;
    st4hi(rhh + o,        make_float4(rx * hlx, ry * hly, rz * hlz, rw * hlw));
    st4hi(rhh + o + 1024, make_float4(rx * hrx, ry * hry, rz * hrz, rw * hrw));
}

template<bool FINAL>
__global__ void e2_kernel(const float* __restrict__ pre2, const float* __restrict__ zb,
                          const half* __restrict__ hph, const half* __restrict__ hpl,
                          half* __restrict__ hoh, half* __restrict__ hol,
                          float* __restrict__ outf, int total4)
{
    int q = blockIdx.x * blockDim.x + threadIdx.x;
    if (q >= total4) return;
    int idx = q * 4;
    int m = idx >> 10, j = idx & 1023;
    size_t o = (size_t)m * 2048 + j;
    float4 z  = *(const float4*)(zb + idx);
    float4 p  = *(const float4*)(pre2 + idx);
    float4 Hh = ld4h(hph + o),        Lh = ld4h(hpl + o);
    float4 Hr = ld4h(hph + o + 1024), Lr = ld4h(hpl + o + 1024);
    float4 r;
    r.x = z.x * ((Hh.x + Lh.x) + (Hr.x + Lr.x)) + (1.f - z.x) * tanhf(p.x);
    r.y = z.y * ((Hh.y + Lh.y) + (Hr.y + Lr.y)) + (1.f - z.y) * tanhf(p.y);
    r.z = z.z * ((Hh.z + Lh.z) + (Hr.z + Lr.z)) + (1.f - z.z) * tanhf(p.z);
    r.w = z.w * ((Hh.w + Lh.w) + (Hr.w + Lr.w)) + (1.f - z.w) * tanhf(p.w);
    if (FINAL) *(float4*)(outf + idx) = r;
    else       st4split(hoh + idx, hol + idx, r);
}

// ================= launch =================
extern "C" void kernel_launch(void* const* d_in, const int* in_sizes, int n_in,
                              void* d_out, int out_size)
{
    const int*   tokens = (const int*)  d_in[0];
    const float* emb    = (const float*)d_in[1];

    PackArgs pa;
    pa.emb = emb;
    pa.Wz  = (const float*)d_in[2];
    pa.bz  = (const float*)d_in[3];
    pa.Uzl = (const float*)d_in[4];
    pa.bzl = (const float*)d_in[5];
    pa.Uzr = (const float*)d_in[6];
    pa.bzr = (const float*)d_in[7];
    pa.br  = (const float*)d_in[9];
    pa.Url = (const float*)d_in[10];
    pa.brl = (const float*)d_in[11];
    pa.Urr = (const float*)d_in[12];
    pa.brr = (const float*)d_in[13];
    pa.Wh  = (const float*)d_in[14];
    pa.bh  = (const float*)d_in[15];
    pa.Uhl = (const float*)d_in[16];
    pa.bhl = (const float*)d_in[17];
    pa.Uhr = (const float*)d_in[18];
    pa.bhr = (const float*)d_in[19];

    half *EMBh, *HB0h, *HB0l, *HB1h, *HB1l, *RHh;
    half *W0h, *W0l, *UZRh, *UHh, *UHl;
    float *PRE, *ZB, *BL0, *BZR, *BH;
    cudaGetSymbolAddress((void**)&EMBh, g_EMBh);
    cudaGetSymbolAddress((void**)&HB0h, g_HB0h);
    cudaGetSymbolAddress((void**)&HB0l, g_HB0l);
    cudaGetSymbolAddress((void**)&HB1h, g_HB1h);
    cudaGetSymbolAddress((void**)&HB1l, g_HB1l);
    cudaGetSymbolAddress((void**)&RHh,  g_RHh);
    cudaGetSymbolAddress((void**)&W0h,  g_W0h);
    cudaGetSymbolAddress((void**)&W0l,  g_W0l);
    cudaGetSymbolAddress((void**)&UZRh, g_UZRh);
    cudaGetSymbolAddress((void**)&UHh,  g_UHh);
    cudaGetSymbolAddress((void**)&UHl,  g_UHl);
    cudaGetSymbolAddress((void**)&PRE,  g_PRE);
    cudaGetSymbolAddress((void**)&ZB,   g_Z);
    cudaGetSymbolAddress((void**)&BL0,  g_BL0);
    cudaGetSymbolAddress((void**)&BZR,  g_BZR);
    cudaGetSymbolAddress((void**)&BH,   g_BH);

    cudaFuncSetAttribute(gemm_mma_kernel<2, 128, true,  false>,
                         cudaFuncAttributeMaxDynamicSharedMemorySize, GemmCfg<2,128>::smem);
    cudaFuncSetAttribute(gemm_mma_kernel<2, 128, false, false>,
                         cudaFuncAttributeMaxDynamicSharedMemorySize, GemmCfg<2,128>::smem);
    cudaFuncSetAttribute(gemm_mma_kernel<1, 128, false, false>,
                         cudaFuncAttributeMaxDynamicSharedMemorySize, GemmCfg<1,128>::smem);
    cudaFuncSetAttribute(gemm_mma_kernel<1, 64, false, true>,
                         cudaFuncAttributeMaxDynamicSharedMemorySize, GemmCfg<1,64>::smem);
    cudaFuncSetAttribute(gemm_mma_kernel<2, 64, false, true>,
                         cudaFuncAttributeMaxDynamicSharedMemorySize, GemmCfg<2,64>::smem);

    // ---- launch 0: megapack ----
    {
        int nblocks = NB_EMB + 2 * NB_W + 4 + 6 * NB_U;
        megapack_kernel<<<nblocks, 256>>>(pa);
    }

    // ---- launch 1: level-0 GEMM ; launch 2: e0 ----
    {
        dim3 grid(2 * HDIM / BN, M0 / 128);
        gemm_mma_kernel<2, 128, true, false><<<grid, 256, GemmCfg<2,128>::smem>>>(
            EMBh, tokens, W0h, W0l, BL0, PRE, M0, 2 * HDIM, EDIM);
        int total4 = M0 * HDIM / 4;
        e0_kernel<<<(total4 + 255) / 256, 256>>>(PRE, HB0h, HB0l, total4);
    }

    // ---- tree levels (launch 3 = level-1 GEMM1, the ncu target) ----
    half* hph = HB0h; half* hpl = HB0l;
    int n = SEQ, lvl = 0;
    while (n > 1) {
        int Mn = BATCH * (n / 2);
        bool final = (n / 2 == 1);
        bool sk = (Mn <= 512);
        half* hoh = (lvl & 1) ? HB0h : HB1h;
        half* hol = (lvl & 1) ? HB0l : HB1l;
        int total4 = Mn * HDIM / 4;

        // GEMM1 (gates, 1-term): h_hi @ UZRh + [bz|br]
        if (sk) {
            int t4 = Mn * 2 * HDIM / 4;
            seed_kernel<<<(t4 + 255) / 256, 256>>>(PRE, BZR, t4, 2 * HDIM - 1);
            dim3 grid(2 * HDIM / BN, Mn / 64, NSPLIT);
            gemm_mma_kernel<1, 64, false, true><<<grid, 128, GemmCfg<1,64>::smem>>>(
                hph, nullptr, UZRh, nullptr, BZR, PRE, Mn, 2 * HDIM, 2 * HDIM);
        } else {
            dim3 grid(2 * HDIM / BN, Mn / 128);
            gemm_mma_kernel<1, 128, false, false><<<grid, 256, GemmCfg<1,128>::smem>>>(
                hph, nullptr, UZRh, nullptr, BZR, PRE, Mn, 2 * HDIM, 2 * HDIM);
        }
        e1_kernel<<<(total4 + 255) / 256, 256>>>(PRE, hph, hpl, ZB, RHh, total4);
        // GEMM2 (h-tilde, 2-term): rh_hi @ (UHh+UHl) + bh
        if (sk) {
            int t4 = Mn * HDIM / 4;
            seed_kernel<<<(t4 + 255) / 256, 256>>>(PRE, BH, t4, HDIM - 1);
            dim3 grid(HDIM / BN, Mn / 64, NSPLIT);
            gemm_mma_kernel<2, 64, false, true><<<grid, 128, GemmCfg<2,64>::smem>>>(
                RHh, nullptr, UHh, UHl, BH, PRE, Mn, HDIM, 2 * HDIM);
        } else {
            dim3 grid(HDIM / BN, Mn / 128);
            gemm_mma_kernel<2, 128, false, false><<<grid, 256, GemmCfg<2,128>::smem>>>(
                RHh, nullptr, UHh, UHl, BH, PRE, Mn, HDIM, 2 * HDIM);
        }
        if (final)
            e2_kernel<true><<<(total4 + 255) / 256, 256>>>(PRE, ZB, hph, hpl, nullptr, nullptr,
                                                           (float*)d_out, total4);
        else
            e2_kernel<false><<<(total4 + 255) / 256, 256>>>(PRE, ZB, hph, hpl, hoh, hol,
                                                            nullptr, total4);

        hph = hoh; hpl = hol;
        n /= 2;
        lvl++;
    }
    (void)in_sizes; (void)n_in; (void)out_size;
}

// round 16
// speedup vs baseline: 2.8885x; 1.2850x over previous
#include <cuda_runtime.h>
#include <cuda_fp16.h>
#include <math.h>
#include <stdint.h>

// ---------------- problem constants ----------------
#define BATCH   64
#define SEQ     512
#define EDIM    512
#define HDIM    1024
#define VOCAB   32000
#define M0      (BATCH*SEQ)      // 32768 level-0 nodes
#define NSPLIT  4

// ---------------- device scratch (allocation-free rule) ----------------
__device__ half  g_EMBh[(size_t)VOCAB * EDIM];
__device__ half  g_HB0h[(size_t)M0 * HDIM];
__device__ half  g_HB0l[(size_t)M0 * HDIM];
__device__ half  g_HB1h[(size_t)(M0/2) * HDIM];
__device__ half  g_HB1l[(size_t)(M0/2) * HDIM];
__device__ half  g_RHh [(size_t)(M0/2) * 2 * HDIM];
__device__ half  g_W0h [(size_t)(2*HDIM) * EDIM];      // [2048][512]  K-major
__device__ half  g_UZRh[(size_t)(2*HDIM) * (2*HDIM)];  // [2048][2048]
__device__ half  g_UHh [(size_t)HDIM * (2*HDIM)];      // [1024][2048]
__device__ float g_PRE[(size_t)M0 * 2 * HDIM];
__device__ float g_Z  [(size_t)(M0/2) * HDIM];
__device__ float g_BL0[2*HDIM];
__device__ float g_BZR[2*HDIM];
__device__ float g_BH [HDIM];

// ================= helpers =================
__device__ __forceinline__ uint32_t smem_u32(const void* p) {
    uint32_t a;
    asm("{ .reg .u64 t; cvta.to.shared.u64 t, %1; cvt.u32.u64 %0, t; }" : "=r"(a) : "l"(p));
    return a;
}
__device__ __forceinline__ void split1(float v, half& h, half& l) {
    h = __float2half_rn(v);
    l = __float2half_rn(v - __half2float(h));
}
__device__ __forceinline__ float4 ld4h(const half* p) {
    uint2 u = *(const uint2*)p;
    __half2 a = *(__half2*)&u.x, b = *(__half2*)&u.y;
    float2 fa = __half22float2(a), fb = __half22float2(b);
    return make_float4(fa.x, fa.y, fb.x, fb.y);
}
__device__ __forceinline__ void st4split(half* ph, half* pl, float4 v) {
    half h0, l0, h1, l1, h2, l2, h3, l3;
    split1(v.x, h0, l0); split1(v.y, h1, l1);
    split1(v.z, h2, l2); split1(v.w, h3, l3);
    __half2 H0 = __halves2half2(h0, h1), H1 = __halves2half2(h2, h3);
    __half2 L0 = __halves2half2(l0, l1), L1 = __halves2half2(l2, l3);
    uint2 uh, ul;
    uh.x = *(uint32_t*)&H0; uh.y = *(uint32_t*)&H1;
    ul.x = *(uint32_t*)&L0; ul.y = *(uint32_t*)&L1;
    *(uint2*)ph = uh; *(uint2*)pl = ul;
}
__device__ __forceinline__ void st4hi(half* ph, float4 v) {
    __half2 a = __floats2half2_rn(v.x, v.y);
    __half2 b = __floats2half2_rn(v.z, v.w);
    uint2 u;
    u.x = *(uint32_t*)&a; u.y = *(uint32_t*)&b;
    *(uint2*)ph = u;
}

#define CP16(dst, src) asm volatile("cp.async.cg.shared.global [%0], [%1], 16;" :: "r"(dst), "l"(src))
#define CP_COMMIT()    asm volatile("cp.async.commit_group;" ::: "memory")
#define CP_WAIT(n)     asm volatile("cp.async.wait_group %0;" :: "n"(n) : "memory")

#define LDSM4(r0, r1, r2, r3, addr)                                              \
    asm volatile("ldmatrix.sync.aligned.m8n8.x4.shared.b16 {%0,%1,%2,%3}, [%4];" \
        : "=r"(r0), "=r"(r1), "=r"(r2), "=r"(r3) : "r"(addr))

#define MMA16816(d, a, b0, b1)                                                   \
    asm volatile("mma.sync.aligned.m16n8k16.row.col.f32.f16.f16.f32 "            \
        "{%0,%1,%2,%3}, {%4,%5,%6,%7}, {%8,%9}, {%0,%1,%2,%3};"                  \
        : "+f"((d)[0]), "+f"((d)[1]), "+f"((d)[2]), "+f"((d)[3])                  \
        : "r"((a)[0]), "r"((a)[1]), "r"((a)[2]), "r"((a)[3]), "r"(b0), "r"(b1))

__device__ __forceinline__ float sigmf(float x) { return 1.f / (1.f + expf(-x)); }

// ================= megapack =================
#define NB_EMB   16000
#define NB_W     512
#define NB_U     1024

struct PackArgs {
    const float *emb, *Wz, *Wh, *Uzl, *Url, *Uzr, *Urr, *Uhl, *Uhr;
    const float *bz, *bzl, *bzr, *br, *brl, *brr, *bh, *bhl, *bhr;
};

__device__ void do_transpose_hi(const float* __restrict__ src,
                                half* __restrict__ dh,
                                int R, int C, int dpitch, int blk, int tid)
{
    __shared__ float t[32][33];
    int gx = C / 32;
    int c0 = (blk % gx) * 32, r0 = (blk / gx) * 32;
    int x = tid & 31, y = tid >> 5;   // 32 x 8
    #pragma unroll
    for (int i = 0; i < 32; i += 8) {
        t[y + i][x] = src[(size_t)(r0 + y + i) * C + (c0 + x)];
    }
    __syncthreads();
    #pragma unroll
    for (int i = 0; i < 32; i += 8) {
        int c = c0 + y + i, r = r0 + x;
        dh[(size_t)c * dpitch + r] = __float2half_rn(t[x][y + i]);
    }
}

__global__ void __launch_bounds__(256) megapack_kernel(PackArgs a)
{
    const int tid = threadIdx.x;
    int blk = blockIdx.x;

    if (blk < NB_EMB) {   // emb -> hi plane
        int q = blk * 256 + tid;
        const int total4 = VOCAB * EDIM / 4;
        if (q < total4) {
            int idx = q * 4;
            float4 v = *(const float4*)(a.emb + idx);
            st4hi(g_EMBh + idx, v);
        }
        return;
    }
    blk -= NB_EMB;
    if (blk < 2 * NB_W) { // W0 transposes (hi only)
        if (blk < NB_W) do_transpose_hi(a.Wz, g_W0h, 512, 1024, 512, blk, tid);
        else            do_transpose_hi(a.Wh, g_W0h + (size_t)1024*512,
                                        512, 1024, 512, blk - NB_W, tid);
        return;
    }
    blk -= 2 * NB_W;
    if (blk < 4) {
        int i = blk * 256 + tid;
        float bzs = a.bz[i] + a.bzl[i] + a.bzr[i];
        float brs = a.br[i] + a.brl[i] + a.brr[i];
        float bhs = a.bh[i] + a.bhl[i] + a.bhr[i];
        g_BZR[i] = bzs; g_BZR[1024 + i] = brs;
        g_BH[i]  = bhs;
        g_BL0[i] = bzs; g_BL0[1024 + i] = bhs;
        return;
    }
    blk -= 4;
    {
        int which = blk / NB_U, b = blk % NB_U;
        switch (which) {
            case 0: do_transpose_hi(a.Uzl, g_UZRh, 1024, 1024, 2048, b, tid); break;
            case 1: do_transpose_hi(a.Url, g_UZRh + (size_t)1024*2048, 1024, 1024, 2048, b, tid); break;
            case 2: do_transpose_hi(a.Uzr, g_UZRh + 1024, 1024, 1024, 2048, b, tid); break;
            case 3: do_transpose_hi(a.Urr, g_UZRh + (size_t)1024*2048 + 1024, 1024, 1024, 2048, b, tid); break;
            case 4: do_transpose_hi(a.Uhl, g_UHh, 1024, 1024, 2048, b, tid); break;
            default: do_transpose_hi(a.Uhr, g_UHh + 1024, 1024, 1024, 2048, b, tid); break;
        }
    }
}

// seed PRE with broadcast bias (for split-K accumulation)
__global__ void seed_kernel(float* __restrict__ pre, const float* __restrict__ bias,
                            int total4, int Nmask)
{
    int q = blockIdx.x * blockDim.x + threadIdx.x;
    if (q >= total4) return;
    int idx = q * 4;
    int c = idx & Nmask;
    *(float4*)(pre + idx) = *(const float4*)(bias + c);
}

// ================= mma GEMM (1-term), cp.async 3-stage =================
// C = Ah @ Bh^T (+bias). BMT = CTA M tile (64 or 128). BN=128 fixed.
// Warp tile 32x64: BMT/32 m-warps x 2 n-warps, TC = BMT*2 threads.
#define BN 128
#define BK 32
#define PAD_B 80
#define NSTAGE 3

template<int BMT>
struct GemmCfg {
    static constexpr int TC    = BMT * 2;             // threads
    static constexpr int WM    = BMT / 32;            // m-warps
    static constexpr int RT    = BMT + 128;           // rows per stage
    static constexpr int nseg  = RT * 4 / TC;         // 16B segs per thread
    static constexpr int oBH   = BMT * PAD_B;
    static constexpr int stage = RT * PAD_B;          // 20480 / 15360
    static constexpr int smem  = NSTAGE * stage;      // 61440 / 46080
    static constexpr int occ   = (BMT == 128) ? 2 : 4;
};

template<int BMT, bool GATHER, bool SPLITK>
__global__ void __launch_bounds__(GemmCfg<BMT>::TC, GemmCfg<BMT>::occ)
gemm_mma_kernel(const half* __restrict__ Ah,
                const int* __restrict__ tok,
                const half* __restrict__ Bh,
                const float* __restrict__ bias,
                float* __restrict__ C, int M, int N, int K)
{
    using Cfg = GemmCfg<BMT>;
    extern __shared__ char smem[];
    const uint32_t sb = smem_u32(smem);
    const int tid  = threadIdx.x;
    const int lane = tid & 31;
    const int wid  = tid >> 5;
    const int warp_m = wid % Cfg::WM;
    const int warp_n = wid / Cfg::WM;
    const int bm = blockIdx.y * BMT, bn = blockIdx.x * BN;

    const int NTfull = K / BK;
    const int NT = SPLITK ? NTfull / NSPLIT : NTfull;
    const int gb = SPLITK ? (int)(blockIdx.z * NT) * 64 : 0;

    // ---- cp.async mapping ----
    const char* srcp[Cfg::nseg];
    uint32_t    dsto[Cfg::nseg];
    #pragma unroll
    for (int i = 0; i < Cfg::nseg; i++) {
        int s   = tid + Cfg::TC * i;
        int row = s >> 2;
        int sg  = (s & 3) * 16;
        dsto[i] = (uint32_t)(row * PAD_B + sg);
        if (row < BMT) {
            int gr = bm + row;
            size_t ar = GATHER ? (size_t)__ldg(&tok[gr]) : (size_t)gr;
            srcp[i] = (const char*)(Ah + ar * K) + sg + gb;
        } else {
            srcp[i] = (const char*)(Bh + (size_t)(bn + row - BMT) * K) + sg + gb;
        }
    }

    auto issue = [&](int kt) {
        if (kt < NT) {
            const uint32_t d = sb + (kt % NSTAGE) * Cfg::stage;
            const int g = kt * 64;
            #pragma unroll
            for (int i = 0; i < Cfg::nseg; i++) CP16(d + dsto[i], srcp[i] + g);
        }
        CP_COMMIT();
    };

    const uint32_t a_lane_off = (uint32_t)((warp_m * 32 + (lane & 15)) * PAD_B + ((lane >> 4) * 8) * 2);
    const uint32_t b_lane_off = (uint32_t)((warp_n * 64 + ((lane >> 4) << 3) + (lane & 7)) * PAD_B
                                           + (((lane >> 3) & 1) * 8) * 2);

    float acc[2][8][4];
    #pragma unroll
    for (int mt = 0; mt < 2; mt++)
        #pragma unroll
        for (int t = 0; t < 8; t++)
            #pragma unroll
            for (int j = 0; j < 4; j++) acc[mt][t][j] = 0.f;

    issue(0);
    issue(1);

#define LDSM_A(arr, ks)                                                           \
    _Pragma("unroll")                                                             \
    for (int mt = 0; mt < 2; mt++) {                                              \
        uint32_t ad = sbase + a_lane_off + mt * (16 * PAD_B) + (ks) * 32;         \
        LDSM4(arr[mt][0], arr[mt][1], arr[mt][2], arr[mt][3], ad);                \
    }
#define LDSM_B(arr, ks)                                                           \
    _Pragma("unroll")                                                             \
    for (int ng = 0; ng < 4; ng++) {                                              \
        uint32_t bd = sbase + b_lane_off + ng * (16 * PAD_B) + (ks) * 32;         \
        LDSM4(arr[ng][0], arr[ng][1], arr[ng][2], arr[ng][3], bd + Cfg::oBH);     \
    }
#define DO_MMA1(aF, bF)                                                           \
    _Pragma("unroll")                                                             \
    for (int mt = 0; mt < 2; mt++)                                                \
        _Pragma("unroll")                                                         \
        for (int ng = 0; ng < 4; ng++)                                            \
            _Pragma("unroll")                                                     \
            for (int p = 0; p < 2; p++)                                           \
                MMA16816(acc[mt][ng * 2 + p], aF[mt], bF[ng][2 * p], bF[ng][2 * p + 1]);

    for (int kt = 0; kt < NT; kt++) {
        CP_WAIT(1);
        __syncthreads();
        const uint32_t sbase = sb + (kt % NSTAGE) * Cfg::stage;

        uint32_t a0[2][4], b0[4][4];
        LDSM_A(a0, 0); LDSM_B(b0, 0);
        issue(kt + 2);
        DO_MMA1(a0, b0);
        uint32_t a1[2][4], b1[4][4];
        LDSM_A(a1, 1); LDSM_B(b1, 1);
        DO_MMA1(a1, b1);
    }

    // ---- epilogue ----
    const int r0e = bm + warp_m * 32 + (lane >> 2);
    const int c0e = bn + warp_n * 64 + (lane & 3) * 2;
    #pragma unroll
    for (int mt = 0; mt < 2; mt++) {
        const int row = r0e + mt * 16;
        #pragma unroll
        for (int t = 0; t < 8; t++) {
            const int col = c0e + t * 8;
            if (SPLITK) {
                atomicAdd(C + (size_t)row * N + col,           acc[mt][t][0]);
                atomicAdd(C + (size_t)row * N + col + 1,       acc[mt][t][1]);
                atomicAdd(C + (size_t)(row + 8) * N + col,     acc[mt][t][2]);
                atomicAdd(C + (size_t)(row + 8) * N + col + 1, acc[mt][t][3]);
            } else {
                const float b0 = bias[col], b1 = bias[col + 1];
                float2 v0 = make_float2(acc[mt][t][0] + b0, acc[mt][t][1] + b1);
                *(float2*)(C + (size_t)row * N + col) = v0;
                float2 v1 = make_float2(acc[mt][t][2] + b0, acc[mt][t][3] + b1);
                *(float2*)(C + (size_t)(row + 8) * N + col) = v1;
            }
        }
    }
}

// ================= elementwise epilogues =================
__global__ void e0_kernel(const float* __restrict__ pre,
                          half* __restrict__ hh, half* __restrict__ hl, int total4)
{
    int q = blockIdx.x * blockDim.x + threadIdx.x;
    if (q >= total4) return;
    int idx = q * 4;
    int m = idx >> 10, j = idx & 1023;
    size_t o = (size_t)m * 2048 + j;
    float4 zp = *(const float4*)(pre + o);
    float4 hp = *(const float4*)(pre + o + 1024);
    float4 r;
    r.x = (1.f - sigmf(zp.x)) * tanhf(hp.x);
    r.y = (1.f - sigmf(zp.y)) * tanhf(hp.y);
    r.z = (1.f - sigmf(zp.z)) * tanhf(hp.z);
    r.w = (1.f - sigmf(zp.w)) * tanhf(hp.w);
    st4split(hh + idx, hl + idx, r);
}

__global__ void e1_kernel(const float* __restrict__ pre,
                          const half* __restrict__ hph, const half* __restrict__ hpl,
                          float* __restrict__ zb,
                          half* __restrict__ rhh, int total4)
{
    int q = blockIdx.x * blockDim.x + threadIdx.x;
    if (q >= total4) return;
    int idx = q * 4;
    int m = idx >> 10, j = idx & 1023;
    size_t o = (size_t)m * 2048 + j;
    float4 zp = *(const float4*)(pre + o);
    float4 rp = *(const float4*)(pre + o + 1024);
    float4 Hh = ld4h(hph + o),        Lh = ld4h(hpl + o);
    float4 Hr = ld4h(hph + o + 1024), Lr = ld4h(hpl + o + 1024);
    float hlx = Hh.x + Lh.x, hly = Hh.y + Lh.y, hlz = Hh.z + Lh.z, hlw = Hh.w + Lh.w;
    float hrx = Hr.x + Lr.x, hry = Hr.y + Lr.y, hrz = Hr.z + Lr.z, hrw = Hr.w + Lr.w;
    float4 z;
    z.x = sigmf(zp.x); z.y = sigmf(zp.y); z.z = sigmf(zp.z); z.w = sigmf(zp.w);
    float rx = sigmf(rp.x), ry = sigmf(rp.y), rz = sigmf(rp.z), rw = sigmf(rp.w);
    *(float4*)(zb + idx) = z;
    st4hi(rhh + o,        make_float4(rx * hlx, ry * hly, rz * hlz, rw * hlw));
    st4hi(rhh + o + 1024, make_float4(rx * hrx, ry * hry, rz * hrz, rw * hrw));
}

template<bool FINAL>
__global__ void e2_kernel(const float* __restrict__ pre2, const float* __restrict__ zb,
                          const half* __restrict__ hph, const half* __restrict__ hpl,
                          half* __restrict__ hoh, half* __restrict__ hol,
                          float* __restrict__ outf, int total4)
{
    int q = blockIdx.x * blockDim.x + threadIdx.x;
    if (q >= total4) return;
    int idx = q * 4;
    int m = idx >> 10, j = idx & 1023;
    size_t o = (size_t)m * 2048 + j;
    float4 z  = *(const float4*)(zb + idx);
    float4 p  = *(const float4*)(pre2 + idx);
    float4 Hh = ld4h(hph + o),        Lh = ld4h(hpl + o);
    float4 Hr = ld4h(hph + o + 1024), Lr = ld4h(hpl + o + 1024);
    float4 r;
    r.x = z.x * ((Hh.x + Lh.x) + (Hr.x + Lr.x)) + (1.f - z.x) * tanhf(p.x);
    r.y = z.y * ((Hh.y + Lh.y) + (Hr.y + Lr.y)) + (1.f - z.y) * tanhf(p.y);
    r.z = z.z * ((Hh.z + Lh.z) + (Hr.z + Lr.z)) + (1.f - z.z) * tanhf(p.z);
    r.w = z.w * ((Hh.w + Lh.w) + (Hr.w + Lr.w)) + (1.f - z.w) * tanhf(p.w);
    if (FINAL) *(float4*)(outf + idx) = r;
    else       st4split(hoh + idx, hol + idx, r);
}

// ================= launch =================
extern "C" void kernel_launch(void* const* d_in, const int* in_sizes, int n_in,
                              void* d_out, int out_size)
{
    const int*   tokens = (const int*)  d_in[0];
    const float* emb    = (const float*)d_in[1];

    PackArgs pa;
    pa.emb = emb;
    pa.Wz  = (const float*)d_in[2];
    pa.bz  = (const float*)d_in[3];
    pa.Uzl = (const float*)d_in[4];
    pa.bzl = (const float*)d_in[5];
    pa.Uzr = (const float*)d_in[6];
    pa.bzr = (const float*)d_in[7];
    pa.br  = (const float*)d_in[9];
    pa.Url = (const float*)d_in[10];
    pa.brl = (const float*)d_in[11];
    pa.Urr = (const float*)d_in[12];
    pa.brr = (const float*)d_in[13];
    pa.Wh  = (const float*)d_in[14];
    pa.bh  = (const float*)d_in[15];
    pa.Uhl = (const float*)d_in[16];
    pa.bhl = (const float*)d_in[17];
    pa.Uhr = (const float*)d_in[18];
    pa.bhr = (const float*)d_in[19];

    half *EMBh, *HB0h, *HB0l, *HB1h, *HB1l, *RHh;
    half *W0h, *UZRh, *UHh;
    float *PRE, *ZB, *BL0, *BZR, *BH;
    cudaGetSymbolAddress((void**)&EMBh, g_EMBh);
    cudaGetSymbolAddress((void**)&HB0h, g_HB0h);
    cudaGetSymbolAddress((void**)&HB0l, g_HB0l);
    cudaGetSymbolAddress((void**)&HB1h, g_HB1h);
    cudaGetSymbolAddress((void**)&HB1l, g_HB1l);
    cudaGetSymbolAddress((void**)&RHh,  g_RHh);
    cudaGetSymbolAddress((void**)&W0h,  g_W0h);
    cudaGetSymbolAddress((void**)&UZRh, g_UZRh);
    cudaGetSymbolAddress((void**)&UHh,  g_UHh);
    cudaGetSymbolAddress((void**)&PRE,  g_PRE);
    cudaGetSymbolAddress((void**)&ZB,   g_Z);
    cudaGetSymbolAddress((void**)&BL0,  g_BL0);
    cudaGetSymbolAddress((void**)&BZR,  g_BZR);
    cudaGetSymbolAddress((void**)&BH,   g_BH);

    cudaFuncSetAttribute(gemm_mma_kernel<128, true,  false>,
                         cudaFuncAttributeMaxDynamicSharedMemorySize, GemmCfg<128>::smem);
    cudaFuncSetAttribute(gemm_mma_kernel<128, false, false>,
                         cudaFuncAttributeMaxDynamicSharedMemorySize, GemmCfg<128>::smem);
    cudaFuncSetAttribute(gemm_mma_kernel<64, false, true>,
                         cudaFuncAttributeMaxDynamicSharedMemorySize, GemmCfg<64>::smem);

    // ---- launch 0: megapack ----
    {
        int nblocks = NB_EMB + 2 * NB_W + 4 + 6 * NB_U;
        megapack_kernel<<<nblocks, 256>>>(pa);
    }

    // ---- launch 1: level-0 GEMM ; launch 2: e0 ----
    {
        dim3 grid(2 * HDIM / BN, M0 / 128);
        gemm_mma_kernel<128, true, false><<<grid, 256, GemmCfg<128>::smem>>>(
            EMBh, tokens, W0h, BL0, PRE, M0, 2 * HDIM, EDIM);
        int total4 = M0 * HDIM / 4;
        e0_kernel<<<(total4 + 255) / 256, 256>>>(PRE, HB0h, HB0l, total4);
    }

    // ---- tree levels (launch 3 = level-1 GEMM1, the ncu target) ----
    half* hph = HB0h; half* hpl = HB0l;
    int n = SEQ, lvl = 0;
    while (n > 1) {
        int Mn = BATCH * (n / 2);
        bool final = (n / 2 == 1);
        bool sk = (Mn <= 512);
        half* hoh = (lvl & 1) ? HB0h : HB1h;
        half* hol = (lvl & 1) ? HB0l : HB1l;
        int total4 = Mn * HDIM / 4;

        // GEMM1 (gates): h_hi @ UZRh + [bz|br]
        if (sk) {
            int t4 = Mn * 2 * HDIM / 4;
            seed_kernel<<<(t4 + 255) / 256, 256>>>(PRE, BZR, t4, 2 * HDIM - 1);
            dim3 grid(2 * HDIM / BN, Mn / 64, NSPLIT);
            gemm_mma_kernel<64, false, true><<<grid, 128, GemmCfg<64>::smem>>>(
                hph, nullptr, UZRh, BZR, PRE, Mn, 2 * HDIM, 2 * HDIM);
        } else {
            dim3 grid(2 * HDIM / BN, Mn / 128);
            gemm_mma_kernel<128, false, false><<<grid, 256, GemmCfg<128>::smem>>>(
                hph, nullptr, UZRh, BZR, PRE, Mn, 2 * HDIM, 2 * HDIM);
        }
        e1_kernel<<<(total4 + 255) / 256, 256>>>(PRE, hph, hpl, ZB, RHh, total4);
        // GEMM2 (h-tilde): rh_hi @ UHh + bh
        if (sk) {
            int t4 = Mn * HDIM / 4;
            seed_kernel<<<(t4 + 255) / 256, 256>>>(PRE, BH, t4, HDIM - 1);
            dim3 grid(HDIM / BN, Mn / 64, NSPLIT);
            gemm_mma_kernel<64, false, true><<<grid, 128, GemmCfg<64>::smem>>>(
                RHh, nullptr, UHh, BH, PRE, Mn, HDIM, 2 * HDIM);
        } else {
            dim3 grid(HDIM / BN, Mn / 128);
            gemm_mma_kernel<128, false, false><<<grid, 256, GemmCfg<128>::smem>>>(
                RHh, nullptr, UHh, BH, PRE, Mn, HDIM, 2 * HDIM);
        }
        if (final)
            e2_kernel<true><<<(total4 + 255) / 256, 256>>>(PRE, ZB, hph, hpl, nullptr, nullptr,
                                                           (float*)d_out, total4);
        else
            e2_kernel<false><<<(total4 + 255) / 256, 256>>>(PRE, ZB, hph, hpl, hoh, hol,
                                                            nullptr, total4);

        hph = hoh; hpl = hol;
        n /= 2;
        lvl++;
    }
    (void)in_sizes; (void)n_in; (void)out_size;
}